// round 1
// baseline (speedup 1.0000x reference)
#include <cuda_runtime.h>
#include <math.h>

#define NCELLS 121
#define DM 128
#define NH 4
#define DH 32
#define NL 6
#define FF 512
#define BATCH 256
#define NTHREADS 512
#define NWARPS 16

// shared layout (floats):
// sh   : NCELLS*DM      = 15488   residual stream
// sa   : NCELLS*DM      = 15488   LN output / GEMM input
// sb   : 16384                    GAT projection (15488) OR FFN hidden block 32x512
// ssrc : NCELLS*NH      = 484
// sdst : NCELLS*NH      = 484
#define SMEM_FLOATS (NCELLS*DM*2 + 16384 + NCELLS*NH*2)
#define SMEM_BYTES  (SMEM_FLOATS * 4)

__device__ __forceinline__ float warp_sum(float v) {
#pragma unroll
    for (int o = 16; o; o >>= 1) v += __shfl_xor_sync(0xffffffffu, v, o);
    return v;
}

__device__ __forceinline__ float gelu_exact(float x) {
    return 0.5f * x * (1.0f + erff(x * 0.70710678118654752440f));
}

// LayerNorm over rows of [NCELLS][DM]; one warp per row.
__device__ __forceinline__ void ln_rows(const float* __restrict__ src,
                                        float* __restrict__ dst,
                                        const float* __restrict__ g,
                                        const float* __restrict__ bta,
                                        int lane, int warp, bool do_gelu) {
    for (int n = warp; n < NCELLS; n += NWARPS) {
        const float* r = src + n * DM;
        float v[4];
#pragma unroll
        for (int i = 0; i < 4; i++) v[i] = r[lane + 32 * i];
        float m = warp_sum(v[0] + v[1] + v[2] + v[3]) * (1.0f / DM);
        float var = 0.0f;
#pragma unroll
        for (int i = 0; i < 4; i++) { v[i] -= m; var += v[i] * v[i]; }
        var = warp_sum(var) * (1.0f / DM);
        float inv = rsqrtf(var + 1e-5f);
        float* o = dst + n * DM;
#pragma unroll
        for (int i = 0; i < 4; i++) {
            int d = lane + 32 * i;
            float y = v[i] * inv * g[d] + bta[d];
            o[d] = do_gelu ? gelu_exact(y) : y;
        }
    }
}

__global__ __launch_bounds__(NTHREADS, 1)
void gateau_kernel(const float* __restrict__ x,
                   const float* __restrict__ enc_W,  const float* __restrict__ enc_b,
                   const float* __restrict__ enc_ln_g, const float* __restrict__ enc_ln_b,
                   const float* __restrict__ ln1_g,  const float* __restrict__ ln1_b,
                   const float* __restrict__ gat_W,
                   const float* __restrict__ a_src,  const float* __restrict__ a_dst,
                   const float* __restrict__ ln2_g,  const float* __restrict__ ln2_b,
                   const float* __restrict__ ff_W1,  const float* __restrict__ ff_b1,
                   const float* __restrict__ ff_W2,  const float* __restrict__ ff_b2,
                   const float* __restrict__ fn_g,   const float* __restrict__ fn_b,
                   float* __restrict__ out) {
    extern __shared__ float smem[];
    float* sh   = smem;
    float* sa   = sh + NCELLS * DM;
    float* sb   = sa + NCELLS * DM;
    float* ssrc = sb + 16384;
    float* sdst = ssrc + NCELLS * NH;

    const int b = blockIdx.x;
    const int tid = threadIdx.x;
    const int lane = tid & 31;
    const int warp = tid >> 5;

    // ---------------- Encoder: x @ enc_W + enc_b -> sa ----------------
    {
        const float* xb = x + (size_t)b * NCELLS * 6;
        for (int idx = tid; idx < NCELLS * DM; idx += NTHREADS) {
            int n = idx >> 7, d = idx & 127;
            float acc = enc_b[d];
#pragma unroll
            for (int k = 0; k < 6; k++) acc += xb[n * 6 + k] * enc_W[k * DM + d];
            sa[idx] = acc;
        }
    }
    __syncthreads();
    // LN + GELU -> sh
    ln_rows(sa, sh, enc_ln_g, enc_ln_b, lane, warp, true);
    __syncthreads();

    // ---------------- Layers ----------------
    for (int li = 0; li < NL; li++) {
        // LN1 -> sa
        ln_rows(sh, sa, ln1_g + li * DM, ln1_b + li * DM, lane, warp, false);
        __syncthreads();

        // GAT projection: sb = sa @ gat_W[li]  (121x128 @ 128x128)
        {
            const float4* W4 = (const float4*)(gat_W + (size_t)li * DM * DM);
            for (int it = tid; it < NCELLS * 32; it += NTHREADS) {
                int n = it >> 5, c4 = it & 31;
                const float* arow = sa + n * DM;
                float4 acc = make_float4(0.f, 0.f, 0.f, 0.f);
#pragma unroll 4
                for (int k = 0; k < DM; k++) {
                    float xv = arow[k];
                    float4 w = W4[k * 32 + c4];
                    acc.x += xv * w.x; acc.y += xv * w.y;
                    acc.z += xv * w.z; acc.w += xv * w.w;
                }
                ((float4*)sb)[n * 32 + c4] = acc;
            }
        }
        __syncthreads();

        // attention scores per (node, head)
        for (int it = tid; it < NCELLS * NH; it += NTHREADS) {
            int n = it >> 2, hh = it & 3;
            const float* hp = sb + n * DM + hh * DH;
            const float* as = a_src + ((size_t)li * NH + hh) * DH;
            const float* ad = a_dst + ((size_t)li * NH + hh) * DH;
            float s1 = 0.f, s2 = 0.f;
#pragma unroll
            for (int k = 0; k < DH; k++) { float v = hp[k]; s1 += v * as[k]; s2 += v * ad[k]; }
            ssrc[it] = s1; sdst[it] = s2;
        }
        __syncthreads();

        // aggregation: warp per dst node, softmax over <=6 hex neighbors
        for (int n = warp; n < NCELLS; n += NWARPS) {
            int q = n / 11, r = n - 11 * q;
            const int dq[6] = { 1, -1, 0, 0, 1, -1 };
            const int dr[6] = { 0, 0, 1, -1, -1, 1 };
            int js[6]; int cnt = 0;
#pragma unroll
            for (int e = 0; e < 6; e++) {
                int nq = q + dq[e], nr = r + dr[e];
                if (nq >= 0 && nq < 11 && nr >= 0 && nr < 11) js[cnt++] = nq * 11 + nr;
            }
#pragma unroll
            for (int hh = 0; hh < NH; hh++) {
                float sd = sdst[n * NH + hh];
                float ex[6]; float m = -1e30f;
                for (int c = 0; c < cnt; c++) {
                    float e = ssrc[js[c] * NH + hh] + sd;
                    e = (e > 0.f) ? e : 0.2f * e;
                    ex[c] = e; m = fmaxf(m, e);
                }
                float s = 0.f;
                for (int c = 0; c < cnt; c++) { ex[c] = expf(ex[c] - m); s += ex[c]; }
                float inv = 1.0f / (s + 1e-10f);
                float acc = 0.f;
                for (int c = 0; c < cnt; c++)
                    acc += ex[c] * inv * sb[js[c] * DM + hh * DH + lane];
                sh[n * DM + hh * DH + lane] += acc;
            }
        }
        __syncthreads();

        // LN2 -> sa
        ln_rows(sh, sa, ln2_g + li * DM, ln2_b + li * DM, lane, warp, false);
        __syncthreads();

        // FFN: process 32-node row blocks; hidden block in sb (32x512)
        {
            const float4* W1_4 = (const float4*)(ff_W1 + (size_t)li * DM * FF);
            const float4* W2_4 = (const float4*)(ff_W2 + (size_t)li * FF * DM);
            const float4* b1_4 = (const float4*)(ff_b1 + (size_t)li * FF);
            const float4* b2_4 = (const float4*)(ff_b2 + (size_t)li * DM);
            for (int blk = 0; blk < 4; blk++) {
                int row0 = blk * 32;
                int rows = min(32, NCELLS - row0);
                // GEMM1 + bias + GELU: sb[rows][512] = gelu(sa_blk @ W1 + b1)
                for (int it = tid; it < rows * 128; it += NTHREADS) {
                    int rr = it >> 7, c4 = it & 127;
                    const float* arow = sa + (row0 + rr) * DM;
                    float4 acc = b1_4[c4];
#pragma unroll 4
                    for (int k = 0; k < DM; k++) {
                        float xv = arow[k];
                        float4 w = W1_4[k * 128 + c4];
                        acc.x += xv * w.x; acc.y += xv * w.y;
                        acc.z += xv * w.z; acc.w += xv * w.w;
                    }
                    acc.x = gelu_exact(acc.x); acc.y = gelu_exact(acc.y);
                    acc.z = gelu_exact(acc.z); acc.w = gelu_exact(acc.w);
                    ((float4*)sb)[rr * 128 + c4] = acc;
                }
                __syncthreads();
                // GEMM2 + bias + residual: sh_blk += sb @ W2 + b2
                for (int it = tid; it < rows * 32; it += NTHREADS) {
                    int rr = it >> 5, c4 = it & 31;
                    const float* hrow = sb + rr * FF;
                    float4 acc = b2_4[c4];
#pragma unroll 4
                    for (int k = 0; k < FF; k++) {
                        float xv = hrow[k];
                        float4 w = W2_4[k * 32 + c4];
                        acc.x += xv * w.x; acc.y += xv * w.y;
                        acc.z += xv * w.z; acc.w += xv * w.w;
                    }
                    float4* hout = (float4*)(sh + (row0 + rr) * DM);
                    float4 cur = hout[c4];
                    cur.x += acc.x; cur.y += acc.y; cur.z += acc.z; cur.w += acc.w;
                    hout[c4] = cur;
                }
                __syncthreads();
            }
        }
    }

    // ---------------- Final LN -> global out ----------------
    ln_rows(sh, out + (size_t)b * NCELLS * DM, fn_g, fn_b, lane, warp, false);
}

extern "C" void kernel_launch(void* const* d_in, const int* in_sizes, int n_in,
                              void* d_out, int out_size) {
    const float* x        = (const float*)d_in[0];
    const float* enc_W    = (const float*)d_in[1];
    const float* enc_b    = (const float*)d_in[2];
    const float* enc_ln_g = (const float*)d_in[3];
    const float* enc_ln_b = (const float*)d_in[4];
    const float* ln1_g    = (const float*)d_in[5];
    const float* ln1_b    = (const float*)d_in[6];
    const float* gat_W    = (const float*)d_in[7];
    const float* a_src    = (const float*)d_in[8];
    const float* a_dst    = (const float*)d_in[9];
    const float* ln2_g    = (const float*)d_in[10];
    const float* ln2_b    = (const float*)d_in[11];
    const float* ff_W1    = (const float*)d_in[12];
    const float* ff_b1    = (const float*)d_in[13];
    const float* ff_W2    = (const float*)d_in[14];
    const float* ff_b2    = (const float*)d_in[15];
    const float* fn_g     = (const float*)d_in[16];
    const float* fn_b     = (const float*)d_in[17];
    // d_in[18] = edge_index (int32) — adjacency is derived arithmetically from the 11x11 hex grid.

    cudaFuncSetAttribute(gateau_kernel,
                         cudaFuncAttributeMaxDynamicSharedMemorySize, SMEM_BYTES);

    gateau_kernel<<<BATCH, NTHREADS, SMEM_BYTES>>>(
        x, enc_W, enc_b, enc_ln_g, enc_ln_b,
        ln1_g, ln1_b, gat_W, a_src, a_dst,
        ln2_g, ln2_b, ff_W1, ff_b1, ff_W2, ff_b2,
        fn_g, fn_b, (float*)d_out);
}

// round 3
// speedup vs baseline: 2.0308x; 2.0308x over previous
#include <cuda_runtime.h>
#include <math.h>

typedef unsigned long long ull;

#define NCELLS 121
#define DM 128
#define NH 4
#define DH 32
#define NL 6
#define FF 512
#define BATCH 256
#define NTHREADS 512
#define NWARPS 16
#define FBLK 32

// smem floats: sh 15488 | sa 15488 | scratch 16384 (GAT proj 121x128 or FFN hidden 32x512) | scores 968
#define SMEM_FLOATS (15488*2 + 16384 + 484*2)
#define SMEM_BYTES  (SMEM_FLOATS * 4)

union F4U { float4 f4; ull u[2]; float f[4]; };
union F2U { ull u; float f[2]; };

__device__ __forceinline__ ull pack2(float a) {
    ull d; asm("mov.b64 %0, {%1, %1};" : "=l"(d) : "f"(a)); return d;
}
__device__ __forceinline__ void fma2(ull& d, ull a, ull b) {
    asm("fma.rn.f32x2 %0, %1, %2, %0;" : "+l"(d) : "l"(a), "l"(b));
}

__device__ __forceinline__ float warp_sum(float v) {
#pragma unroll
    for (int o = 16; o; o >>= 1) v += __shfl_xor_sync(0xffffffffu, v, o);
    return v;
}

__device__ __forceinline__ float gelu_exact(float x) {
    return 0.5f * x * (1.0f + erff(x * 0.70710678118654752440f));
}

// LayerNorm over rows; one warp per row.
__device__ __forceinline__ void ln_rows(const float* __restrict__ src,
                                        float* __restrict__ dst,
                                        const float* __restrict__ g,
                                        const float* __restrict__ bta,
                                        int lane, int warp, bool do_gelu) {
    for (int n = warp; n < NCELLS; n += NWARPS) {
        const float* r = src + n * DM;
        float v[4];
#pragma unroll
        for (int i = 0; i < 4; i++) v[i] = r[lane + 32 * i];
        float m = warp_sum(v[0] + v[1] + v[2] + v[3]) * (1.0f / DM);
        float var = 0.0f;
#pragma unroll
        for (int i = 0; i < 4; i++) { v[i] -= m; var += v[i] * v[i]; }
        var = warp_sum(var) * (1.0f / DM);
        float inv = rsqrtf(var + 1e-5f);
        float* o = dst + n * DM;
#pragma unroll
        for (int i = 0; i < 4; i++) {
            int d = lane + 32 * i;
            float y = v[i] * inv * g[d] + bta[d];
            o[d] = do_gelu ? gelu_exact(y) : y;
        }
    }
}

// Register-tiled GEMM: O[rowsA][N] = act(A[rowsA][K] @ W[K][N] (+b)) with f32x2 packed FMA.
// Thread computes R rows x CPT cols. Cols are NV float4 groups strided by 4*CG
// so every LDG.128 is warp-coalesced. RESID: O += result.
template<int K, int N, int CPT, int R, bool GELU, bool RESID, bool HASB>
__device__ __forceinline__ void gemm_rt(const float* __restrict__ A, int rowsA,
                                        const float* __restrict__ Wg,
                                        const float* __restrict__ bg,
                                        float* __restrict__ O, int ostride,
                                        int tid) {
    constexpr int CG = N / CPT;          // column groups
    constexpr int NV = CPT / 4;          // float4s per thread
    const int cg = tid % CG;
    const int rg = tid / CG;
    const int r0 = rg * R;
    if (r0 >= rowsA) return;

    const float4* W4 = (const float4*)Wg;

    ull acc[R][NV][2];
#pragma unroll
    for (int v = 0; v < NV; v++) {
        F4U bv;
        if (HASB) bv.f4 = ((const float4*)bg)[cg + v * CG];
        else      bv.f4 = make_float4(0.f, 0.f, 0.f, 0.f);
#pragma unroll
        for (int i = 0; i < R; i++) { acc[i][v][0] = bv.u[0]; acc[i][v][1] = bv.u[1]; }
    }

    int rofs[R];
#pragma unroll
    for (int i = 0; i < R; i++) rofs[i] = min(r0 + i, rowsA - 1) * K;

#pragma unroll 4
    for (int k = 0; k < K; k++) {
        F4U w[NV];
#pragma unroll
        for (int v = 0; v < NV; v++) w[v].f4 = W4[k * (N / 4) + cg + v * CG];
#pragma unroll
        for (int i = 0; i < R; i++) {
            ull av = pack2(A[rofs[i] + k]);
#pragma unroll
            for (int v = 0; v < NV; v++) {
                fma2(acc[i][v][0], av, w[v].u[0]);
                fma2(acc[i][v][1], av, w[v].u[1]);
            }
        }
    }

#pragma unroll
    for (int i = 0; i < R; i++) {
        int r = r0 + i;
        if (r >= rowsA) break;
        float* orow = O + r * ostride;
#pragma unroll
        for (int v = 0; v < NV; v++) {
            int c = (cg + v * CG) * 4;
#pragma unroll
            for (int h = 0; h < 2; h++) {
                F2U p; p.u = acc[i][v][h];
                float v0 = p.f[0], v1 = p.f[1];
                if (GELU) { v0 = gelu_exact(v0); v1 = gelu_exact(v1); }
                if (RESID) { orow[c + 2*h] += v0; orow[c + 2*h + 1] += v1; }
                else       { orow[c + 2*h]  = v0; orow[c + 2*h + 1]  = v1; }
            }
        }
    }
}

__global__ __launch_bounds__(NTHREADS, 1)
void gateau_kernel(const float* __restrict__ x,
                   const float* __restrict__ enc_W,  const float* __restrict__ enc_b,
                   const float* __restrict__ enc_ln_g, const float* __restrict__ enc_ln_b,
                   const float* __restrict__ ln1_g,  const float* __restrict__ ln1_b,
                   const float* __restrict__ gat_W,
                   const float* __restrict__ a_src,  const float* __restrict__ a_dst,
                   const float* __restrict__ ln2_g,  const float* __restrict__ ln2_b,
                   const float* __restrict__ ff_W1,  const float* __restrict__ ff_b1,
                   const float* __restrict__ ff_W2,  const float* __restrict__ ff_b2,
                   const float* __restrict__ fn_g,   const float* __restrict__ fn_b,
                   float* __restrict__ out) {
    extern __shared__ float smem[];
    float* sh   = smem;
    float* sa   = sh + NCELLS * DM;
    float* sbuf = sa + NCELLS * DM;      // GAT projection OR FFN hidden block
    float* ssrc = sbuf + 16384;
    float* sdst = ssrc + NCELLS * NH;

    const int b = blockIdx.x;
    const int tid = threadIdx.x;
    const int lane = tid & 31;
    const int warp = tid >> 5;

    // ---------------- Encoder ----------------
    {
        const float* xb = x + (size_t)b * NCELLS * 6;
        for (int idx = tid; idx < NCELLS * DM; idx += NTHREADS) {
            int n = idx >> 7, d = idx & 127;
            float acc = enc_b[d];
#pragma unroll
            for (int k = 0; k < 6; k++) acc += xb[n * 6 + k] * enc_W[k * DM + d];
            sa[idx] = acc;
        }
    }
    __syncthreads();
    ln_rows(sa, sh, enc_ln_g, enc_ln_b, lane, warp, true);
    __syncthreads();

    // ---------------- Layers ----------------
    for (int li = 0; li < NL; li++) {
        // LN1 -> sa
        ln_rows(sh, sa, ln1_g + li * DM, ln1_b + li * DM, lane, warp, false);
        __syncthreads();

        // GAT projection: sbuf[121][128] = sa @ gat_W[li]
        gemm_rt<DM, DM, 8, 4, false, false, false>(
            sa, NCELLS, gat_W + (size_t)li * DM * DM, nullptr, sbuf, DM, tid);
        __syncthreads();

        // attention scores per (node, head)
        for (int it = tid; it < NCELLS * NH; it += NTHREADS) {
            int n = it >> 2, hh = it & 3;
            const float* hp = sbuf + n * DM + hh * DH;
            const float* as = a_src + ((size_t)li * NH + hh) * DH;
            const float* ad = a_dst + ((size_t)li * NH + hh) * DH;
            float s1 = 0.f, s2 = 0.f;
#pragma unroll
            for (int k = 0; k < DH; k++) { float v = hp[k]; s1 += v * as[k]; s2 += v * ad[k]; }
            ssrc[it] = s1; sdst[it] = s2;
        }
        __syncthreads();

        // aggregation: warp per dst node, softmax over <=6 hex neighbors
        for (int n = warp; n < NCELLS; n += NWARPS) {
            int q = n / 11, r = n - 11 * q;
            const int dq[6] = { 1, -1, 0, 0, 1, -1 };
            const int dr[6] = { 0, 0, 1, -1, -1, 1 };
            int js[6]; int cnt = 0;
#pragma unroll
            for (int e = 0; e < 6; e++) {
                int nq = q + dq[e], nr = r + dr[e];
                if (nq >= 0 && nq < 11 && nr >= 0 && nr < 11) js[cnt++] = nq * 11 + nr;
            }
#pragma unroll
            for (int hh = 0; hh < NH; hh++) {
                float sd = sdst[n * NH + hh];
                float ex[6]; float m = -1e30f;
                for (int c = 0; c < cnt; c++) {
                    float e = ssrc[js[c] * NH + hh] + sd;
                    e = (e > 0.f) ? e : 0.2f * e;
                    ex[c] = e; m = fmaxf(m, e);
                }
                float s = 0.f;
                for (int c = 0; c < cnt; c++) { ex[c] = expf(ex[c] - m); s += ex[c]; }
                float inv = 1.0f / (s + 1e-10f);
                float acc = 0.f;
                for (int c = 0; c < cnt; c++)
                    acc += ex[c] * inv * sbuf[js[c] * DM + hh * DH + lane];
                sh[n * DM + hh * DH + lane] += acc;
            }
        }
        __syncthreads();

        // LN2 -> sa
        ln_rows(sh, sa, ln2_g + li * DM, ln2_b + li * DM, lane, warp, false);
        __syncthreads();

        // FFN in 32-row blocks; hidden (32x512) in sbuf
        const float* W1 = ff_W1 + (size_t)li * DM * FF;
        const float* W2 = ff_W2 + (size_t)li * FF * DM;
        const float* b1 = ff_b1 + (size_t)li * FF;
        const float* b2 = ff_b2 + (size_t)li * DM;
        for (int blk = 0; blk < 4; blk++) {
            int row0 = blk * FBLK;
            int rows = min(FBLK, NCELLS - row0);
            // hidden = gelu(sa_blk @ W1 + b1)
            gemm_rt<DM, FF, 8, 4, true, false, true>(
                sa + row0 * DM, rows, W1, b1, sbuf, FF, tid);
            __syncthreads();
            // sh_blk += hidden @ W2 + b2
            gemm_rt<FF, DM, 4, 2, false, true, true>(
                sbuf, rows, W2, b2, sh + row0 * DM, DM, tid);
            __syncthreads();
        }
    }

    // ---------------- Final LN -> out ----------------
    ln_rows(sh, out + (size_t)b * NCELLS * DM, fn_g, fn_b, lane, warp, false);
}

extern "C" void kernel_launch(void* const* d_in, const int* in_sizes, int n_in,
                              void* d_out, int out_size) {
    const float* x        = (const float*)d_in[0];
    const float* enc_W    = (const float*)d_in[1];
    const float* enc_b    = (const float*)d_in[2];
    const float* enc_ln_g = (const float*)d_in[3];
    const float* enc_ln_b = (const float*)d_in[4];
    const float* ln1_g    = (const float*)d_in[5];
    const float* ln1_b    = (const float*)d_in[6];
    const float* gat_W    = (const float*)d_in[7];
    const float* a_src    = (const float*)d_in[8];
    const float* a_dst    = (const float*)d_in[9];
    const float* ln2_g    = (const float*)d_in[10];
    const float* ln2_b    = (const float*)d_in[11];
    const float* ff_W1    = (const float*)d_in[12];
    const float* ff_b1    = (const float*)d_in[13];
    const float* ff_W2    = (const float*)d_in[14];
    const float* ff_b2    = (const float*)d_in[15];
    const float* fn_g     = (const float*)d_in[16];
    const float* fn_b     = (const float*)d_in[17];
    // d_in[18] = edge_index — adjacency derived arithmetically from the 11x11 hex grid.

    cudaFuncSetAttribute(gateau_kernel,
                         cudaFuncAttributeMaxDynamicSharedMemorySize, SMEM_BYTES);

    gateau_kernel<<<BATCH, NTHREADS, SMEM_BYTES>>>(
        x, enc_W, enc_b, enc_ln_g, enc_ln_b,
        ln1_g, ln1_b, gat_W, a_src, a_dst,
        ln2_g, ln2_b, ff_W1, ff_b1, ff_W2, ff_b2,
        fn_g, fn_b, (float*)d_out);
}

// round 10
// speedup vs baseline: 4.4249x; 2.1789x over previous
#include <cuda_runtime.h>
#include <cuda_bf16.h>
#include <math.h>
#include <stdint.h>

#define NCELLS 121
#define DM 128
#define NH 4
#define NL 6
#define FF 512
#define BATCH 256
#define NTHREADS 512
#define NWARPS 16

// ---------------- smem byte offsets ----------------
#define OFF_SH    0          // residual fp32 [121][128] = 61952
#define OFF_SSRC  61952      // scores 484 f32
#define OFF_SDST  63888      // scores 484 f32
#define OFF_AH    66048      // A hi bf16 [128][136] = 34816  (also GAT out fp32 [128][129] / enc temp)
#define OFF_AL    100864     // A lo bf16 [128][136]
#define OFF_WH    135680     // W chunk hi (<=18432)
#define OFF_WL    154112     // W chunk lo
#define OFF_A2H   172544     // FFN hidden hi bf16 [128][72] = 18432
#define OFF_A2L   190976     // FFN hidden lo
#define SMEM_TOTAL 209408

#define SA 136   // A row stride (bf16 elems)
#define SW 136   // W1/GAT chunk row stride
#define S2 72    // A2 / W2 chunk row stride
#define SBUF_STRIDE 129

// ---------------- preprocessed weights: [N][K] transposed, hi/lo bf16 ----------------
__device__ __align__(16) __nv_bfloat16 g_gatWh[NL*128*128];
__device__ __align__(16) __nv_bfloat16 g_gatWl[NL*128*128];
__device__ __align__(16) __nv_bfloat16 g_W1h[NL*FF*128];
__device__ __align__(16) __nv_bfloat16 g_W1l[NL*FF*128];
__device__ __align__(16) __nv_bfloat16 g_W2h[NL*128*FF];
__device__ __align__(16) __nv_bfloat16 g_W2l[NL*128*FF];

// ---------------- helpers ----------------
__device__ __forceinline__ float warp_sum(float v) {
#pragma unroll
    for (int o = 16; o; o >>= 1) v += __shfl_xor_sync(0xffffffffu, v, o);
    return v;
}
__device__ __forceinline__ float gelu_exact(float x) {
    return 0.5f * x * (1.0f + erff(x * 0.70710678118654752440f));
}

__device__ __forceinline__ void mma_bf16(float* d, const uint32_t* a, const uint32_t* b) {
    asm volatile("mma.sync.aligned.m16n8k16.row.col.f32.bf16.bf16.f32 "
                 "{%0,%1,%2,%3}, {%4,%5,%6,%7}, {%8,%9}, {%0,%1,%2,%3};"
                 : "+f"(d[0]), "+f"(d[1]), "+f"(d[2]), "+f"(d[3])
                 : "r"(a[0]), "r"(a[1]), "r"(a[2]), "r"(a[3]), "r"(b[0]), "r"(b[1]));
}
// A fragment (16x16 bf16 row-major): a0:(r,k0..), a1:(r+8,k0..), a2:(r,k0+8..), a3:(r+8,k0+8..)
template<int STRIDE>
__device__ __forceinline__ void load_afrag(uint32_t* a, const __nv_bfloat16* A,
                                           int m0, int k0, int lane) {
    int r = m0 + (lane >> 2);
    int c = k0 + (lane & 3) * 2;
    a[0] = *(const uint32_t*)(A + r * STRIDE + c);
    a[1] = *(const uint32_t*)(A + (r + 8) * STRIDE + c);
    a[2] = *(const uint32_t*)(A + r * STRIDE + c + 8);
    a[3] = *(const uint32_t*)(A + (r + 8) * STRIDE + c + 8);
}
// B fragment (16x8, stored [N][K] K-contiguous): b0: k0.., b1: k0+8..
template<int STRIDE>
__device__ __forceinline__ void load_bfrag(uint32_t* b, const __nv_bfloat16* B,
                                           int n0, int k0, int lane) {
    int r = n0 + (lane >> 2);
    int c = k0 + (lane & 3) * 2;
    b[0] = *(const uint32_t*)(B + r * STRIDE + c);
    b[1] = *(const uint32_t*)(B + r * STRIDE + c + 8);
}

// 3-pass split GEMM warp tile: MT m16-tiles x NT n8-tiles, KS k16 steps.
// acc layout: acc[(mi*NT+ni)*4 + {0..3}]
template<int MT, int NT, int KS, int SAs, int SBs>
__device__ __forceinline__ void gemm3(const __nv_bfloat16* Ah, const __nv_bfloat16* Al,
                                      const __nv_bfloat16* Bh, const __nv_bfloat16* Bl,
                                      int m0, int n0, int lane, float* acc) {
#pragma unroll
    for (int p = 0; p < 3; p++) {
        const __nv_bfloat16* A = (p == 1) ? Al : Ah;
        const __nv_bfloat16* B = (p == 2) ? Bl : Bh;
#pragma unroll
        for (int ks = 0; ks < KS; ks++) {
            uint32_t af[MT][4], bf[NT][2];
#pragma unroll
            for (int mi = 0; mi < MT; mi++) load_afrag<SAs>(af[mi], A, m0 + mi * 16, ks * 16, lane);
#pragma unroll
            for (int ni = 0; ni < NT; ni++) load_bfrag<SBs>(bf[ni], B, n0 + ni * 8, ks * 16, lane);
#pragma unroll
            for (int mi = 0; mi < MT; mi++)
#pragma unroll
                for (int ni = 0; ni < NT; ni++)
                    mma_bf16(acc + (mi * NT + ni) * 4, af[mi], bf[ni]);
        }
    }
}

// fp32 LayerNorm rows -> fp32 dst
__device__ __forceinline__ void ln_rows(const float* __restrict__ src, float* __restrict__ dst,
                                        const float* __restrict__ g, const float* __restrict__ bta,
                                        int lane, int warp, bool do_gelu) {
    for (int n = warp; n < NCELLS; n += NWARPS) {
        const float* r = src + n * DM;
        float v[4];
#pragma unroll
        for (int i = 0; i < 4; i++) v[i] = r[lane + 32 * i];
        float m = warp_sum(v[0] + v[1] + v[2] + v[3]) * (1.0f / DM);
        float var = 0.0f;
#pragma unroll
        for (int i = 0; i < 4; i++) { v[i] -= m; var += v[i] * v[i]; }
        var = warp_sum(var) * (1.0f / DM);
        float inv = rsqrtf(var + 1e-5f);
        float* o = dst + n * DM;
#pragma unroll
        for (int i = 0; i < 4; i++) {
            int d = lane + 32 * i;
            float y = v[i] * inv * g[d] + bta[d];
            o[d] = do_gelu ? gelu_exact(y) : y;
        }
    }
}

// LN -> bf16 hi/lo split, row-major [128][SA]; rows >= NCELLS zeroed
__device__ __forceinline__ void ln_split(const float* __restrict__ src,
                                         __nv_bfloat16* __restrict__ aH,
                                         __nv_bfloat16* __restrict__ aL,
                                         const float* __restrict__ g, const float* __restrict__ bta,
                                         int lane, int warp) {
    for (int n = warp; n < 128; n += NWARPS) {
        float y[4] = {0.f, 0.f, 0.f, 0.f};
        if (n < NCELLS) {
            const float* r = src + n * DM;
            float v[4];
#pragma unroll
            for (int i = 0; i < 4; i++) v[i] = r[lane + 32 * i];
            float m = warp_sum(v[0] + v[1] + v[2] + v[3]) * (1.0f / DM);
            float var = 0.0f;
#pragma unroll
            for (int i = 0; i < 4; i++) { v[i] -= m; var += v[i] * v[i]; }
            var = warp_sum(var) * (1.0f / DM);
            float inv = rsqrtf(var + 1e-5f);
#pragma unroll
            for (int i = 0; i < 4; i++) y[i] = v[i] * inv * g[lane + 32 * i] + bta[lane + 32 * i];
        }
#pragma unroll
        for (int i = 0; i < 4; i++) {
            int d = lane + 32 * i;
            __nv_bfloat16 h = __float2bfloat16(y[i]);
            __nv_bfloat16 l = __float2bfloat16(y[i] - __bfloat162float(h));
            aH[n * SA + d] = h;
            aL[n * SA + d] = l;
        }
    }
}

// ---------------- weight preprocessing: transpose to [N][K] + split hi/lo ----------------
__global__ void prep_kernel(const float* __restrict__ gat_W,
                            const float* __restrict__ ff_W1,
                            const float* __restrict__ ff_W2) {
    const int PER = 147456;  // 16384 + 65536 + 65536
    int e = blockIdx.x * 256 + threadIdx.x;
    if (e >= NL * PER) return;
    int li = e / PER, r = e % PER;
    float w; size_t dst; __nv_bfloat16 *ph, *pl;
    if (r < 16384) {                       // gat: [n 128][k 128] from W[k][n]
        int n = r >> 7, k = r & 127;
        w = gat_W[(size_t)li * 16384 + k * 128 + n];
        dst = (size_t)li * 16384 + n * 128 + k;
        ph = g_gatWh; pl = g_gatWl;
    } else if (r < 81920) {                // W1: [n 512][k 128] from W1[k][n]
        int e2 = r - 16384; int n = e2 >> 7, k = e2 & 127;
        w = ff_W1[(size_t)li * 65536 + k * 512 + n];
        dst = (size_t)li * 65536 + n * 128 + k;
        ph = g_W1h; pl = g_W1l;
    } else {                               // W2: [n 128][k 512] from W2[k][n]
        int e2 = r - 81920; int n = e2 >> 9, k = e2 & 511;
        w = ff_W2[(size_t)li * 65536 + k * 128 + n];
        dst = (size_t)li * 65536 + n * 512 + k;
        ph = g_W2h; pl = g_W2l;
    }
    __nv_bfloat16 h = __float2bfloat16(w);
    __nv_bfloat16 l = __float2bfloat16(w - __bfloat162float(h));
    ph[dst] = h; pl[dst] = l;
}

// ---------------- main kernel ----------------
__global__ __launch_bounds__(NTHREADS, 1)
void gateau_mma(const float* __restrict__ x,
                const float* __restrict__ enc_W,  const float* __restrict__ enc_b,
                const float* __restrict__ enc_ln_g, const float* __restrict__ enc_ln_b,
                const float* __restrict__ ln1_g,  const float* __restrict__ ln1_b,
                const float* __restrict__ a_src,  const float* __restrict__ a_dst,
                const float* __restrict__ ln2_g,  const float* __restrict__ ln2_b,
                const float* __restrict__ ff_b1,  const float* __restrict__ ff_b2,
                const float* __restrict__ fn_g,   const float* __restrict__ fn_b,
                float* __restrict__ out) {
    extern __shared__ char smem[];
    float* sh   = (float*)(smem + OFF_SH);
    float* ssrc = (float*)(smem + OFF_SSRC);
    float* sdst = (float*)(smem + OFF_SDST);
    __nv_bfloat16* Ah  = (__nv_bfloat16*)(smem + OFF_AH);
    __nv_bfloat16* Al  = (__nv_bfloat16*)(smem + OFF_AL);
    __nv_bfloat16* Wh  = (__nv_bfloat16*)(smem + OFF_WH);
    __nv_bfloat16* Wl  = (__nv_bfloat16*)(smem + OFF_WL);
    __nv_bfloat16* A2h = (__nv_bfloat16*)(smem + OFF_A2H);
    __nv_bfloat16* A2l = (__nv_bfloat16*)(smem + OFF_A2L);
    float* sbufA = (float*)(smem + OFF_AH);   // GAT output fp32 [128][129] / enc temp

    const int b = blockIdx.x;
    const int tid = threadIdx.x;
    const int lane = tid & 31;
    const int warp = tid >> 5;
    const int mw = warp >> 2;       // 0..3
    const int nw = warp & 3;        // 0..3
    const int lr = lane >> 2;       // 0..7
    const int lc = (lane & 3) * 2;  // 0,2,4,6

    // -------- encoder --------
    {
        const float* xb = x + (size_t)b * NCELLS * 6;
        for (int idx = tid; idx < NCELLS * DM; idx += NTHREADS) {
            int n = idx >> 7, d = idx & 127;
            float acc = enc_b[d];
#pragma unroll
            for (int k = 0; k < 6; k++) acc += xb[n * 6 + k] * enc_W[k * DM + d];
            sbufA[idx] = acc;
        }
    }
    __syncthreads();
    ln_rows(sbufA, sh, enc_ln_g, enc_ln_b, lane, warp, true);
    __syncthreads();

    // -------- layers --------
    for (int li = 0; li < NL; li++) {
        // LN1 -> A splits
        ln_split(sh, Ah, Al, ln1_g + li * DM, ln1_b + li * DM, lane, warp);
        __syncthreads();

        // ---- GAT projection: out[128][128] = A @ gatW^T, two 64-col chunks ----
        float accG[32];
#pragma unroll
        for (int i = 0; i < 32; i++) accG[i] = 0.f;
#pragma unroll
        for (int nc = 0; nc < 2; nc++) {
            {   // stage W chunk [64][128] -> [64][136] hi/lo
                const float4* s0 = (const float4*)(g_gatWh + ((size_t)li * 128 + nc * 64) * 128);
                const float4* s1 = (const float4*)(g_gatWl + ((size_t)li * 128 + nc * 64) * 128);
                float4* d0 = (float4*)Wh; float4* d1 = (float4*)Wl;
                for (int i = tid; i < 1024; i += NTHREADS) {
                    int r = i >> 4, j = i & 15;
                    d0[r * 17 + j] = s0[i]; d1[r * 17 + j] = s1[i];
                }
            }
            __syncthreads();
            gemm3<2, 2, 8, SA, SW>(Ah, Al, Wh, Wl, mw * 32, nw * 16, lane, accG + nc * 16);
            __syncthreads();
        }
        // epilogue: write GAT output fp32 stride 129 over A region
#pragma unroll
        for (int nc = 0; nc < 2; nc++)
#pragma unroll
            for (int mi = 0; mi < 2; mi++)
#pragma unroll
                for (int ni = 0; ni < 2; ni++) {
                    int col = nc * 64 + nw * 16 + ni * 8 + lc;
                    const float* d = accG + nc * 16 + (mi * 2 + ni) * 4;
#pragma unroll
                    for (int h = 0; h < 2; h++) {
                        int row = mw * 32 + mi * 16 + lr + h * 8;
                        sbufA[row * SBUF_STRIDE + col]     = d[h * 2];
                        sbufA[row * SBUF_STRIDE + col + 1] = d[h * 2 + 1];
                    }
                }
        __syncthreads();

        // attention scores
        for (int it = tid; it < NCELLS * NH; it += NTHREADS) {
            int n = it >> 2, hh = it & 3;
            const float* hp = sbufA + n * SBUF_STRIDE + hh * 32;
            const float* as = a_src + ((size_t)li * NH + hh) * 32;
            const float* ad = a_dst + ((size_t)li * NH + hh) * 32;
            float s1 = 0.f, s2 = 0.f;
#pragma unroll
            for (int k = 0; k < 32; k++) { float v = hp[k]; s1 += v * as[k]; s2 += v * ad[k]; }
            ssrc[it] = s1; sdst[it] = s2;
        }
        __syncthreads();

        // softmax aggregation over <=6 hex neighbors; += into residual sh
        for (int n = warp; n < NCELLS; n += NWARPS) {
            int q = n / 11, r = n - 11 * q;
            const int dq[6] = { 1, -1, 0, 0, 1, -1 };
            const int dr[6] = { 0, 0, 1, -1, -1, 1 };
            int js[6]; int cnt = 0;
#pragma unroll
            for (int e = 0; e < 6; e++) {
                int nq = q + dq[e], nr = r + dr[e];
                if (nq >= 0 && nq < 11 && nr >= 0 && nr < 11) js[cnt++] = nq * 11 + nr;
            }
#pragma unroll
            for (int hh = 0; hh < NH; hh++) {
                float sd = sdst[n * NH + hh];
                float ex[6]; float m = -1e30f;
                for (int c = 0; c < cnt; c++) {
                    float e = ssrc[js[c] * NH + hh] + sd;
                    e = (e > 0.f) ? e : 0.2f * e;
                    ex[c] = e; m = fmaxf(m, e);
                }
                float s = 0.f;
                for (int c = 0; c < cnt; c++) { ex[c] = expf(ex[c] - m); s += ex[c]; }
                float inv = 1.0f / (s + 1e-10f);
                float acc = 0.f;
                for (int c = 0; c < cnt; c++)
                    acc += ex[c] * inv * sbufA[js[c] * SBUF_STRIDE + hh * 32 + lane];
                sh[n * DM + hh * 32 + lane] += acc;
            }
        }
        __syncthreads();

        // LN2 -> A splits
        ln_split(sh, Ah, Al, ln2_g + li * DM, ln2_b + li * DM, lane, warp);
        __syncthreads();

        // ---- FFN: 8 hidden chunks of 64; FFN2 accumulates in registers ----
        float accF2[32];
#pragma unroll
        for (int i = 0; i < 32; i++) accF2[i] = 0.f;

        for (int c = 0; c < 8; c++) {
            {   // stage W1 chunk [64 hid][128 k] -> [64][136]
                const float4* s0 = (const float4*)(g_W1h + ((size_t)li * FF + c * 64) * 128);
                const float4* s1 = (const float4*)(g_W1l + ((size_t)li * FF + c * 64) * 128);
                float4* d0 = (float4*)Wh; float4* d1 = (float4*)Wl;
                for (int i = tid; i < 1024; i += NTHREADS) {
                    int r = i >> 4, j = i & 15;
                    d0[r * 17 + j] = s0[i]; d1[r * 17 + j] = s1[i];
                }
            }
            __syncthreads();

            // FFN1: hidden[128][64] = A @ W1c^T
            float accF1[16];
#pragma unroll
            for (int i = 0; i < 16; i++) accF1[i] = 0.f;
            gemm3<2, 2, 8, SA, SW>(Ah, Al, Wh, Wl, mw * 32, nw * 16, lane, accF1);
            __syncthreads();  // mma1 done before overwriting Wbuf / A2

            // epilogue: + b1, gelu, split -> A2 (bf16 [128][72])
            {
                const float* b1p = ff_b1 + (size_t)li * FF + c * 64;
#pragma unroll
                for (int mi = 0; mi < 2; mi++)
#pragma unroll
                    for (int ni = 0; ni < 2; ni++) {
                        int col = nw * 16 + ni * 8 + lc;
                        float bb0 = __ldg(b1p + col), bb1 = __ldg(b1p + col + 1);
                        const float* d = accF1 + (mi * 2 + ni) * 4;
#pragma unroll
                        for (int h = 0; h < 2; h++) {
                            int row = mw * 32 + mi * 16 + lr + h * 8;
                            float v0 = gelu_exact(d[h * 2] + bb0);
                            float v1 = gelu_exact(d[h * 2 + 1] + bb1);
                            __nv_bfloat16 h0 = __float2bfloat16(v0);
                            __nv_bfloat16 h1 = __float2bfloat16(v1);
                            __nv_bfloat16 l0 = __float2bfloat16(v0 - __bfloat162float(h0));
                            __nv_bfloat16 l1 = __float2bfloat16(v1 - __bfloat162float(h1));
                            uint32_t ph = ((uint32_t)__bfloat16_as_ushort(h1) << 16) | __bfloat16_as_ushort(h0);
                            uint32_t pl = ((uint32_t)__bfloat16_as_ushort(l1) << 16) | __bfloat16_as_ushort(l0);
                            *(uint32_t*)((char*)A2h + (row * S2 + col) * 2) = ph;
                            *(uint32_t*)((char*)A2l + (row * S2 + col) * 2) = pl;
                        }
                    }
            }
            {   // stage W2 chunk [128 n][64 k] -> [128][72]
                const float4* s0 = (const float4*)(g_W2h + (size_t)li * 65536);
                const float4* s1 = (const float4*)(g_W2l + (size_t)li * 65536);
                float4* d0 = (float4*)Wh; float4* d1 = (float4*)Wl;
                for (int i = tid; i < 1024; i += NTHREADS) {
                    int r = i >> 3, j = i & 7;
                    d0[r * 9 + j] = s0[r * 64 + c * 8 + j];
                    d1[r * 9 + j] = s1[r * 64 + c * 8 + j];
                }
            }
            __syncthreads();

            // FFN2: accumulate out[128][128] += hidden_c @ W2c^T
            gemm3<2, 4, 4, S2, S2>(A2h, A2l, Wh, Wl, mw * 32, nw * 32, lane, accF2);
            __syncthreads();
        }

        // FFN2 epilogue: sh += acc + b2
        {
            const float* b2p = ff_b2 + (size_t)li * DM;
#pragma unroll
            for (int mi = 0; mi < 2; mi++)
#pragma unroll
                for (int ni = 0; ni < 4; ni++) {
                    int col = nw * 32 + ni * 8 + lc;
                    float bb0 = __ldg(b2p + col), bb1 = __ldg(b2p + col + 1);
                    const float* d = accF2 + (mi * 4 + ni) * 4;
#pragma unroll
                    for (int h = 0; h < 2; h++) {
                        int row = mw * 32 + mi * 16 + lr + h * 8;
                        if (row < NCELLS) {
                            sh[row * DM + col]     += d[h * 2] + bb0;
                            sh[row * DM + col + 1] += d[h * 2 + 1] + bb1;
                        }
                    }
                }
        }
        __syncthreads();
    }

    // -------- final LN -> out --------
    ln_rows(sh, out + (size_t)b * NCELLS * DM, fn_g, fn_b, lane, warp, false);
}

extern "C" void kernel_launch(void* const* d_in, const int* in_sizes, int n_in,
                              void* d_out, int out_size) {
    const float* x        = (const float*)d_in[0];
    const float* enc_W    = (const float*)d_in[1];
    const float* enc_b    = (const float*)d_in[2];
    const float* enc_ln_g = (const float*)d_in[3];
    const float* enc_ln_b = (const float*)d_in[4];
    const float* ln1_g    = (const float*)d_in[5];
    const float* ln1_b    = (const float*)d_in[6];
    const float* gat_W    = (const float*)d_in[7];
    const float* a_src    = (const float*)d_in[8];
    const float* a_dst    = (const float*)d_in[9];
    const float* ln2_g    = (const float*)d_in[10];
    const float* ln2_b    = (const float*)d_in[11];
    const float* ff_W1    = (const float*)d_in[12];
    const float* ff_b1    = (const float*)d_in[13];
    const float* ff_W2    = (const float*)d_in[14];
    const float* ff_b2    = (const float*)d_in[15];
    const float* fn_g     = (const float*)d_in[16];
    const float* fn_b     = (const float*)d_in[17];
    // d_in[18] = edge_index — derived arithmetically on-device.

    prep_kernel<<<(NL * 147456 + 255) / 256, 256>>>(gat_W, ff_W1, ff_W2);

    cudaFuncSetAttribute(gateau_mma, cudaFuncAttributeMaxDynamicSharedMemorySize, SMEM_TOTAL);
    gateau_mma<<<BATCH, NTHREADS, SMEM_TOTAL>>>(
        x, enc_W, enc_b, enc_ln_g, enc_ln_b,
        ln1_g, ln1_b, a_src, a_dst,
        ln2_g, ln2_b, ff_b1, ff_b2,
        fn_g, fn_b, (float*)d_out);
}

// round 11
// speedup vs baseline: 5.5188x; 1.2472x over previous
#include <cuda_runtime.h>
#include <cuda_bf16.h>
#include <math.h>
#include <stdint.h>

#define NCELLS 121
#define DM 128
#define NH 4
#define NL 6
#define FF 512
#define BATCH 256
#define NTHREADS 512
#define NWARPS 16

// ---------------- smem byte offsets ----------------
#define OFF_SH    0          // residual fp32 [121][128] = 61952
#define OFF_SSRC  61952      // scores 484 f32
#define OFF_SDST  63888      // scores 484 f32
#define OFF_AH    66048      // A hi bf16 [128][136] = 34816  (also GAT out fp32 [128][129] / enc temp)
#define OFF_AL    100864     // A lo bf16 [128][136]
#define OFF_WH    135680     // W chunk hi (<=18432)
#define OFF_WL    154112     // W chunk lo
#define OFF_A2H   172544     // FFN hidden hi bf16 [128][72] = 18432
#define OFF_A2L   190976     // FFN hidden lo
#define SMEM_TOTAL 209408

#define SA 136   // A row stride (bf16 elems)
#define SW 136   // W1/GAT chunk row stride
#define S2 72    // A2 / W2 chunk row stride
#define SBUF_STRIDE 129

// ---------------- preprocessed weights: [N][K] transposed, hi/lo bf16 ----------------
__device__ __align__(16) __nv_bfloat16 g_gatWh[NL*128*128];
__device__ __align__(16) __nv_bfloat16 g_gatWl[NL*128*128];
__device__ __align__(16) __nv_bfloat16 g_W1h[NL*FF*128];
__device__ __align__(16) __nv_bfloat16 g_W1l[NL*FF*128];
__device__ __align__(16) __nv_bfloat16 g_W2h[NL*128*FF];
__device__ __align__(16) __nv_bfloat16 g_W2l[NL*128*FF];

// ---------------- helpers ----------------
__device__ __forceinline__ float warp_sum(float v) {
#pragma unroll
    for (int o = 16; o; o >>= 1) v += __shfl_xor_sync(0xffffffffu, v, o);
    return v;
}
__device__ __forceinline__ float gelu_exact(float x) {
    return 0.5f * x * (1.0f + erff(x * 0.70710678118654752440f));
}

__device__ __forceinline__ void mma_bf16(float* d, const uint32_t* a, const uint32_t* b) {
    asm volatile("mma.sync.aligned.m16n8k16.row.col.f32.bf16.bf16.f32 "
                 "{%0,%1,%2,%3}, {%4,%5,%6,%7}, {%8,%9}, {%0,%1,%2,%3};"
                 : "+f"(d[0]), "+f"(d[1]), "+f"(d[2]), "+f"(d[3])
                 : "r"(a[0]), "r"(a[1]), "r"(a[2]), "r"(a[3]), "r"(b[0]), "r"(b[1]));
}
__device__ __forceinline__ void ldsm_x4(uint32_t* r, uint32_t addr) {
    asm volatile("ldmatrix.sync.aligned.m8n8.x4.shared.b16 {%0,%1,%2,%3}, [%4];"
                 : "=r"(r[0]), "=r"(r[1]), "=r"(r[2]), "=r"(r[3]) : "r"(addr));
}

// 3-pass split GEMM warp tile with ldmatrix fragment loads.
// MT m16-tiles x NT2 n16-blocks (NT = 2*NT2 n8-tiles), KS k16 steps.
// Loads Ah/Al/Bh/Bl fragments ONCE per k-step, issues AhBh + AlBh + AhBl.
// acc layout: acc[(mi*NT + ni)*4 + {0..3}], ni = nb*2 + half.
template<int MT, int NT2, int KS, int SAs, int SBs>
__device__ __forceinline__ void gemm3(const __nv_bfloat16* Ah, const __nv_bfloat16* Al,
                                      const __nv_bfloat16* Bh, const __nv_bfloat16* Bl,
                                      int m0, int n0, int lane, float* acc) {
    const int blk = lane >> 3, rib = lane & 7;
    // A x4 blocks: (m0,k0),(m0+8,k0),(m0,k0+8),(m0+8,k0+8) -> a0..a3
    const int a_elem = (m0 + (blk & 1) * 8 + rib) * SAs + (blk >> 1) * 8;
    // B x4 blocks over 16-wide n-block: (n0,k0),(n0,k0+8),(n0+8,k0),(n0+8,k0+8) -> b0..b3
    const int b_elem = (n0 + (blk >> 1) * 8 + rib) * SBs + (blk & 1) * 8;

    const uint32_t aH = (uint32_t)__cvta_generic_to_shared(Ah) + a_elem * 2;
    const uint32_t aL = (uint32_t)__cvta_generic_to_shared(Al) + a_elem * 2;
    const uint32_t bH = (uint32_t)__cvta_generic_to_shared(Bh) + b_elem * 2;
    const uint32_t bL = (uint32_t)__cvta_generic_to_shared(Bl) + b_elem * 2;

#pragma unroll
    for (int ks = 0; ks < KS; ks++) {
        uint32_t ah[MT][4], al[MT][4], bh[NT2][4], bl[NT2][4];
#pragma unroll
        for (int mi = 0; mi < MT; mi++) {
            uint32_t off = (uint32_t)(mi * 16 * SAs + ks * 16) * 2;
            ldsm_x4(ah[mi], aH + off);
            ldsm_x4(al[mi], aL + off);
        }
#pragma unroll
        for (int nb = 0; nb < NT2; nb++) {
            uint32_t off = (uint32_t)(nb * 16 * SBs + ks * 16) * 2;
            ldsm_x4(bh[nb], bH + off);
            ldsm_x4(bl[nb], bL + off);
        }
#pragma unroll
        for (int mi = 0; mi < MT; mi++)
#pragma unroll
            for (int nb = 0; nb < NT2; nb++)
#pragma unroll
                for (int half = 0; half < 2; half++) {
                    float* d = acc + (mi * (NT2 * 2) + nb * 2 + half) * 4;
                    const uint32_t* bp_h = &bh[nb][half * 2];
                    const uint32_t* bp_l = &bl[nb][half * 2];
                    mma_bf16(d, ah[mi], bp_h);   // Ah*Bh
                    mma_bf16(d, al[mi], bp_h);   // Al*Bh
                    mma_bf16(d, ah[mi], bp_l);   // Ah*Bl
                }
    }
}

// fp32 LayerNorm rows -> fp32 dst
__device__ __forceinline__ void ln_rows(const float* __restrict__ src, float* __restrict__ dst,
                                        const float* __restrict__ g, const float* __restrict__ bta,
                                        int lane, int warp, bool do_gelu) {
    for (int n = warp; n < NCELLS; n += NWARPS) {
        const float* r = src + n * DM;
        float v[4];
#pragma unroll
        for (int i = 0; i < 4; i++) v[i] = r[lane + 32 * i];
        float m = warp_sum(v[0] + v[1] + v[2] + v[3]) * (1.0f / DM);
        float var = 0.0f;
#pragma unroll
        for (int i = 0; i < 4; i++) { v[i] -= m; var += v[i] * v[i]; }
        var = warp_sum(var) * (1.0f / DM);
        float inv = rsqrtf(var + 1e-5f);
        float* o = dst + n * DM;
#pragma unroll
        for (int i = 0; i < 4; i++) {
            int d = lane + 32 * i;
            float y = v[i] * inv * g[d] + bta[d];
            o[d] = do_gelu ? gelu_exact(y) : y;
        }
    }
}

// LN -> bf16 hi/lo split, row-major [128][SA]; rows >= NCELLS zeroed
__device__ __forceinline__ void ln_split(const float* __restrict__ src,
                                         __nv_bfloat16* __restrict__ aH,
                                         __nv_bfloat16* __restrict__ aL,
                                         const float* __restrict__ g, const float* __restrict__ bta,
                                         int lane, int warp) {
    for (int n = warp; n < 128; n += NWARPS) {
        float y[4] = {0.f, 0.f, 0.f, 0.f};
        if (n < NCELLS) {
            const float* r = src + n * DM;
            float v[4];
#pragma unroll
            for (int i = 0; i < 4; i++) v[i] = r[lane + 32 * i];
            float m = warp_sum(v[0] + v[1] + v[2] + v[3]) * (1.0f / DM);
            float var = 0.0f;
#pragma unroll
            for (int i = 0; i < 4; i++) { v[i] -= m; var += v[i] * v[i]; }
            var = warp_sum(var) * (1.0f / DM);
            float inv = rsqrtf(var + 1e-5f);
#pragma unroll
            for (int i = 0; i < 4; i++) y[i] = v[i] * inv * g[lane + 32 * i] + bta[lane + 32 * i];
        }
#pragma unroll
        for (int i = 0; i < 4; i++) {
            int d = lane + 32 * i;
            __nv_bfloat16 h = __float2bfloat16(y[i]);
            __nv_bfloat16 l = __float2bfloat16(y[i] - __bfloat162float(h));
            aH[n * SA + d] = h;
            aL[n * SA + d] = l;
        }
    }
}

// ---------------- weight preprocessing: transpose to [N][K] + split hi/lo ----------------
__global__ void prep_kernel(const float* __restrict__ gat_W,
                            const float* __restrict__ ff_W1,
                            const float* __restrict__ ff_W2) {
    const int PER = 147456;  // 16384 + 65536 + 65536
    int e = blockIdx.x * 256 + threadIdx.x;
    if (e >= NL * PER) return;
    int li = e / PER, r = e % PER;
    float w; size_t dst; __nv_bfloat16 *ph, *pl;
    if (r < 16384) {                       // gat: [n 128][k 128] from W[k][n]
        int n = r >> 7, k = r & 127;
        w = gat_W[(size_t)li * 16384 + k * 128 + n];
        dst = (size_t)li * 16384 + n * 128 + k;
        ph = g_gatWh; pl = g_gatWl;
    } else if (r < 81920) {                // W1: [n 512][k 128] from W1[k][n]
        int e2 = r - 16384; int n = e2 >> 7, k = e2 & 127;
        w = ff_W1[(size_t)li * 65536 + k * 512 + n];
        dst = (size_t)li * 65536 + n * 128 + k;
        ph = g_W1h; pl = g_W1l;
    } else {                               // W2: [n 128][k 512] from W2[k][n]
        int e2 = r - 81920; int n = e2 >> 9, k = e2 & 511;
        w = ff_W2[(size_t)li * 65536 + k * 128 + n];
        dst = (size_t)li * 65536 + n * 512 + k;
        ph = g_W2h; pl = g_W2l;
    }
    __nv_bfloat16 h = __float2bfloat16(w);
    __nv_bfloat16 l = __float2bfloat16(w - __bfloat162float(h));
    ph[dst] = h; pl[dst] = l;
}

// ---------------- main kernel ----------------
__global__ __launch_bounds__(NTHREADS, 1)
void gateau_mma(const float* __restrict__ x,
                const float* __restrict__ enc_W,  const float* __restrict__ enc_b,
                const float* __restrict__ enc_ln_g, const float* __restrict__ enc_ln_b,
                const float* __restrict__ ln1_g,  const float* __restrict__ ln1_b,
                const float* __restrict__ a_src,  const float* __restrict__ a_dst,
                const float* __restrict__ ln2_g,  const float* __restrict__ ln2_b,
                const float* __restrict__ ff_b1,  const float* __restrict__ ff_b2,
                const float* __restrict__ fn_g,   const float* __restrict__ fn_b,
                float* __restrict__ out) {
    extern __shared__ char smem[];
    float* sh   = (float*)(smem + OFF_SH);
    float* ssrc = (float*)(smem + OFF_SSRC);
    float* sdst = (float*)(smem + OFF_SDST);
    __nv_bfloat16* Ah  = (__nv_bfloat16*)(smem + OFF_AH);
    __nv_bfloat16* Al  = (__nv_bfloat16*)(smem + OFF_AL);
    __nv_bfloat16* Wh  = (__nv_bfloat16*)(smem + OFF_WH);
    __nv_bfloat16* Wl  = (__nv_bfloat16*)(smem + OFF_WL);
    __nv_bfloat16* A2h = (__nv_bfloat16*)(smem + OFF_A2H);
    __nv_bfloat16* A2l = (__nv_bfloat16*)(smem + OFF_A2L);
    float* sbufA = (float*)(smem + OFF_AH);   // GAT output fp32 [128][129] / enc temp

    const int b = blockIdx.x;
    const int tid = threadIdx.x;
    const int lane = tid & 31;
    const int warp = tid >> 5;
    const int mw = warp >> 2;       // 0..3
    const int nw = warp & 3;        // 0..3
    const int lr = lane >> 2;       // 0..7
    const int lc = (lane & 3) * 2;  // 0,2,4,6

    // -------- encoder --------
    {
        const float* xb = x + (size_t)b * NCELLS * 6;
        for (int idx = tid; idx < NCELLS * DM; idx += NTHREADS) {
            int n = idx >> 7, d = idx & 127;
            float acc = enc_b[d];
#pragma unroll
            for (int k = 0; k < 6; k++) acc += xb[n * 6 + k] * enc_W[k * DM + d];
            sbufA[idx] = acc;
        }
    }
    __syncthreads();
    ln_rows(sbufA, sh, enc_ln_g, enc_ln_b, lane, warp, true);
    __syncthreads();

    // -------- layers --------
    for (int li = 0; li < NL; li++) {
        // LN1 -> A splits
        ln_split(sh, Ah, Al, ln1_g + li * DM, ln1_b + li * DM, lane, warp);
        __syncthreads();

        // ---- GAT projection: out[128][128] = A @ gatW^T, two 64-col chunks ----
        float accG[32];
#pragma unroll
        for (int i = 0; i < 32; i++) accG[i] = 0.f;
#pragma unroll
        for (int nc = 0; nc < 2; nc++) {
            {   // stage W chunk [64][128] -> [64][136] hi/lo
                const float4* s0 = (const float4*)(g_gatWh + ((size_t)li * 128 + nc * 64) * 128);
                const float4* s1 = (const float4*)(g_gatWl + ((size_t)li * 128 + nc * 64) * 128);
                float4* d0 = (float4*)Wh; float4* d1 = (float4*)Wl;
                for (int i = tid; i < 1024; i += NTHREADS) {
                    int r = i >> 4, j = i & 15;
                    d0[r * 17 + j] = s0[i]; d1[r * 17 + j] = s1[i];
                }
            }
            __syncthreads();
            gemm3<2, 1, 8, SA, SW>(Ah, Al, Wh, Wl, mw * 32, nw * 16, lane, accG + nc * 16);
            __syncthreads();
        }
        // epilogue: write GAT output fp32 stride 129 over A region
#pragma unroll
        for (int nc = 0; nc < 2; nc++)
#pragma unroll
            for (int mi = 0; mi < 2; mi++)
#pragma unroll
                for (int ni = 0; ni < 2; ni++) {
                    int col = nc * 64 + nw * 16 + ni * 8 + lc;
                    const float* d = accG + nc * 16 + (mi * 2 + ni) * 4;
#pragma unroll
                    for (int h = 0; h < 2; h++) {
                        int row = mw * 32 + mi * 16 + lr + h * 8;
                        sbufA[row * SBUF_STRIDE + col]     = d[h * 2];
                        sbufA[row * SBUF_STRIDE + col + 1] = d[h * 2 + 1];
                    }
                }
        __syncthreads();

        // attention scores
        for (int it = tid; it < NCELLS * NH; it += NTHREADS) {
            int n = it >> 2, hh = it & 3;
            const float* hp = sbufA + n * SBUF_STRIDE + hh * 32;
            const float* as = a_src + ((size_t)li * NH + hh) * 32;
            const float* ad = a_dst + ((size_t)li * NH + hh) * 32;
            float s1 = 0.f, s2 = 0.f;
#pragma unroll
            for (int k = 0; k < 32; k++) { float v = hp[k]; s1 += v * as[k]; s2 += v * ad[k]; }
            ssrc[it] = s1; sdst[it] = s2;
        }
        __syncthreads();

        // softmax aggregation over <=6 hex neighbors; += into residual sh
        for (int n = warp; n < NCELLS; n += NWARPS) {
            int q = n / 11, r = n - 11 * q;
            const int dq[6] = { 1, -1, 0, 0, 1, -1 };
            const int dr[6] = { 0, 0, 1, -1, -1, 1 };
            int js[6]; int cnt = 0;
#pragma unroll
            for (int e = 0; e < 6; e++) {
                int nq = q + dq[e], nr = r + dr[e];
                if (nq >= 0 && nq < 11 && nr >= 0 && nr < 11) js[cnt++] = nq * 11 + nr;
            }
#pragma unroll
            for (int hh = 0; hh < NH; hh++) {
                float sd = sdst[n * NH + hh];
                float ex[6]; float m = -1e30f;
                for (int c = 0; c < cnt; c++) {
                    float e = ssrc[js[c] * NH + hh] + sd;
                    e = (e > 0.f) ? e : 0.2f * e;
                    ex[c] = e; m = fmaxf(m, e);
                }
                float s = 0.f;
                for (int c = 0; c < cnt; c++) { ex[c] = expf(ex[c] - m); s += ex[c]; }
                float inv = 1.0f / (s + 1e-10f);
                float acc = 0.f;
                for (int c = 0; c < cnt; c++)
                    acc += ex[c] * inv * sbufA[js[c] * SBUF_STRIDE + hh * 32 + lane];
                sh[n * DM + hh * 32 + lane] += acc;
            }
        }
        __syncthreads();

        // LN2 -> A splits
        ln_split(sh, Ah, Al, ln2_g + li * DM, ln2_b + li * DM, lane, warp);
        __syncthreads();

        // ---- FFN: 8 hidden chunks of 64; FFN2 accumulates in registers ----
        float accF2[32];
#pragma unroll
        for (int i = 0; i < 32; i++) accF2[i] = 0.f;

        for (int c = 0; c < 8; c++) {
            {   // stage W1 chunk [64 hid][128 k] -> [64][136]
                const float4* s0 = (const float4*)(g_W1h + ((size_t)li * FF + c * 64) * 128);
                const float4* s1 = (const float4*)(g_W1l + ((size_t)li * FF + c * 64) * 128);
                float4* d0 = (float4*)Wh; float4* d1 = (float4*)Wl;
                for (int i = tid; i < 1024; i += NTHREADS) {
                    int r = i >> 4, j = i & 15;
                    d0[r * 17 + j] = s0[i]; d1[r * 17 + j] = s1[i];
                }
            }
            __syncthreads();

            // FFN1: hidden[128][64] = A @ W1c^T
            float accF1[16];
#pragma unroll
            for (int i = 0; i < 16; i++) accF1[i] = 0.f;
            gemm3<2, 1, 8, SA, SW>(Ah, Al, Wh, Wl, mw * 32, nw * 16, lane, accF1);
            __syncthreads();  // mma1 done before overwriting Wbuf / A2

            // epilogue: + b1, gelu, split -> A2 (bf16 [128][72])
            {
                const float* b1p = ff_b1 + (size_t)li * FF + c * 64;
#pragma unroll
                for (int mi = 0; mi < 2; mi++)
#pragma unroll
                    for (int ni = 0; ni < 2; ni++) {
                        int col = nw * 16 + ni * 8 + lc;
                        float bb0 = __ldg(b1p + col), bb1 = __ldg(b1p + col + 1);
                        const float* d = accF1 + (mi * 2 + ni) * 4;
#pragma unroll
                        for (int h = 0; h < 2; h++) {
                            int row = mw * 32 + mi * 16 + lr + h * 8;
                            float v0 = gelu_exact(d[h * 2] + bb0);
                            float v1 = gelu_exact(d[h * 2 + 1] + bb1);
                            __nv_bfloat16 h0 = __float2bfloat16(v0);
                            __nv_bfloat16 h1 = __float2bfloat16(v1);
                            __nv_bfloat16 l0 = __float2bfloat16(v0 - __bfloat162float(h0));
                            __nv_bfloat16 l1 = __float2bfloat16(v1 - __bfloat162float(h1));
                            uint32_t ph = ((uint32_t)__bfloat16_as_ushort(h1) << 16) | __bfloat16_as_ushort(h0);
                            uint32_t pl = ((uint32_t)__bfloat16_as_ushort(l1) << 16) | __bfloat16_as_ushort(l0);
                            *(uint32_t*)((char*)A2h + (row * S2 + col) * 2) = ph;
                            *(uint32_t*)((char*)A2l + (row * S2 + col) * 2) = pl;
                        }
                    }
            }
            {   // stage W2 chunk [128 n][64 k] -> [128][72]
                const float4* s0 = (const float4*)(g_W2h + (size_t)li * 65536);
                const float4* s1 = (const float4*)(g_W2l + (size_t)li * 65536);
                float4* d0 = (float4*)Wh; float4* d1 = (float4*)Wl;
                for (int i = tid; i < 1024; i += NTHREADS) {
                    int r = i >> 3, j = i & 7;
                    d0[r * 9 + j] = s0[r * 64 + c * 8 + j];
                    d1[r * 9 + j] = s1[r * 64 + c * 8 + j];
                }
            }
            __syncthreads();

            // FFN2: accumulate out[128][128] += hidden_c @ W2c^T
            gemm3<2, 2, 4, S2, S2>(A2h, A2l, Wh, Wl, mw * 32, nw * 32, lane, accF2);
            __syncthreads();
        }

        // FFN2 epilogue: sh += acc + b2
        {
            const float* b2p = ff_b2 + (size_t)li * DM;
#pragma unroll
            for (int mi = 0; mi < 2; mi++)
#pragma unroll
                for (int ni = 0; ni < 4; ni++) {
                    int col = nw * 32 + ni * 8 + lc;
                    float bb0 = __ldg(b2p + col), bb1 = __ldg(b2p + col + 1);
                    const float* d = accF2 + (mi * 4 + ni) * 4;
#pragma unroll
                    for (int h = 0; h < 2; h++) {
                        int row = mw * 32 + mi * 16 + lr + h * 8;
                        if (row < NCELLS) {
                            sh[row * DM + col]     += d[h * 2] + bb0;
                            sh[row * DM + col + 1] += d[h * 2 + 1] + bb1;
                        }
                    }
                }
        }
        __syncthreads();
    }

    // -------- final LN -> out --------
    ln_rows(sh, out + (size_t)b * NCELLS * DM, fn_g, fn_b, lane, warp, false);
}

extern "C" void kernel_launch(void* const* d_in, const int* in_sizes, int n_in,
                              void* d_out, int out_size) {
    const float* x        = (const float*)d_in[0];
    const float* enc_W    = (const float*)d_in[1];
    const float* enc_b    = (const float*)d_in[2];
    const float* enc_ln_g = (const float*)d_in[3];
    const float* enc_ln_b = (const float*)d_in[4];
    const float* ln1_g    = (const float*)d_in[5];
    const float* ln1_b    = (const float*)d_in[6];
    const float* gat_W    = (const float*)d_in[7];
    const float* a_src    = (const float*)d_in[8];
    const float* a_dst    = (const float*)d_in[9];
    const float* ln2_g    = (const float*)d_in[10];
    const float* ln2_b    = (const float*)d_in[11];
    const float* ff_W1    = (const float*)d_in[12];
    const float* ff_b1    = (const float*)d_in[13];
    const float* ff_W2    = (const float*)d_in[14];
    const float* ff_b2    = (const float*)d_in[15];
    const float* fn_g     = (const float*)d_in[16];
    const float* fn_b     = (const float*)d_in[17];
    // d_in[18] = edge_index — derived arithmetically on-device.

    prep_kernel<<<(NL * 147456 + 255) / 256, 256>>>(gat_W, ff_W1, ff_W2);

    cudaFuncSetAttribute(gateau_mma, cudaFuncAttributeMaxDynamicSharedMemorySize, SMEM_TOTAL);
    gateau_mma<<<BATCH, NTHREADS, SMEM_TOTAL>>>(
        x, enc_W, enc_b, enc_ln_g, enc_ln_b,
        ln1_g, ln1_b, a_src, a_dst,
        ln2_g, ln2_b, ff_b1, ff_b2,
        fn_g, fn_b, (float*)d_out);
}

// round 12
// speedup vs baseline: 5.8010x; 1.0511x over previous
#include <cuda_runtime.h>
#include <cuda_bf16.h>
#include <math.h>
#include <stdint.h>

#define NCELLS 121
#define DM 128
#define NH 4
#define NL 6
#define FF 512
#define BATCH 256
#define NTHREADS 1024
#define NWARPS 32

// ---------------- smem byte offsets ----------------
#define OFF_SH    0          // residual fp32 [121][128] = 61952
#define OFF_SSRC  61952
#define OFF_SDST  63888
#define OFF_AH    66048      // A hi bf16 [128][136]  (also GAT out fp32 [128][129] / enc temp)
#define OFF_AL    100864     // A lo bf16 [128][136]
#define OFF_WH    135680     // W region (36864 B contiguous): W1 chunk hi/lo OR gatW hi OR W2 hi/lo
#define OFF_WL    154112
#define OFF_A2H   172544     // A2 region (36864 B): FFN hidden hi/lo OR gatW lo
#define OFF_A2L   190976
#define SMEM_TOTAL 209408

#define SA 136   // A row stride (bf16 elems)
#define SW 136   // W1/GAT row stride
#define S2 72    // A2 / W2 row stride
#define SBUF_STRIDE 129

// ---------------- preprocessed weights ----------------
__device__ __align__(16) __nv_bfloat16 g_gatWh[NL*128*128];
__device__ __align__(16) __nv_bfloat16 g_gatWl[NL*128*128];
__device__ __align__(16) __nv_bfloat16 g_W1h[NL*FF*128];
__device__ __align__(16) __nv_bfloat16 g_W1l[NL*FF*128];
__device__ __align__(16) __nv_bfloat16 g_W2h[NL*8*128*64];   // dense per chunk [li][c][n 128][kk 64]
__device__ __align__(16) __nv_bfloat16 g_W2l[NL*8*128*64];

// ---------------- helpers ----------------
__device__ __forceinline__ float warp_sum(float v) {
#pragma unroll
    for (int o = 16; o; o >>= 1) v += __shfl_xor_sync(0xffffffffu, v, o);
    return v;
}
__device__ __forceinline__ float gelu_exact(float x) {
    return 0.5f * x * (1.0f + erff(x * 0.70710678118654752440f));
}
__device__ __forceinline__ void mma_bf16(float* d, const uint32_t* a, const uint32_t* b) {
    asm volatile("mma.sync.aligned.m16n8k16.row.col.f32.bf16.bf16.f32 "
                 "{%0,%1,%2,%3}, {%4,%5,%6,%7}, {%8,%9}, {%0,%1,%2,%3};"
                 : "+f"(d[0]), "+f"(d[1]), "+f"(d[2]), "+f"(d[3])
                 : "r"(a[0]), "r"(a[1]), "r"(a[2]), "r"(a[3]), "r"(b[0]), "r"(b[1]));
}
__device__ __forceinline__ void ldsm_x4(uint32_t* r, uint32_t addr) {
    asm volatile("ldmatrix.sync.aligned.m8n8.x4.shared.b16 {%0,%1,%2,%3}, [%4];"
                 : "=r"(r[0]), "=r"(r[1]), "=r"(r[2]), "=r"(r[3]) : "r"(addr));
}
__device__ __forceinline__ void cp16(uint32_t dst, const void* src) {
    asm volatile("cp.async.cg.shared.global [%0], [%1], 16;" :: "r"(dst), "l"(src));
}
#define CP_WAIT_ALL() asm volatile("cp.async.wait_all;" ::: "memory")
__device__ __forceinline__ uint32_t s2u(const void* p) {
    return (uint32_t)__cvta_generic_to_shared(p);
}

// 3-pass split GEMM warp tile, ldmatrix loads, pass-outer MMA order for ILP.
// MT m16-tiles x NT2 n16-blocks, KS k16 steps. acc[(mi*NT2*2 + nb*2 + half)*4 +{0..3}]
template<int MT, int NT2, int KS, int SAs, int SBs>
__device__ __forceinline__ void gemm3(const __nv_bfloat16* Ah, const __nv_bfloat16* Al,
                                      const __nv_bfloat16* Bh, const __nv_bfloat16* Bl,
                                      int m0, int n0, int lane, float* acc) {
    const int blk = lane >> 3, rib = lane & 7;
    const int a_elem = (m0 + (blk & 1) * 8 + rib) * SAs + (blk >> 1) * 8;
    const int b_elem = (n0 + (blk >> 1) * 8 + rib) * SBs + (blk & 1) * 8;
    const uint32_t aH = s2u(Ah) + a_elem * 2;
    const uint32_t aL = s2u(Al) + a_elem * 2;
    const uint32_t bH = s2u(Bh) + b_elem * 2;
    const uint32_t bL = s2u(Bl) + b_elem * 2;

#pragma unroll
    for (int ks = 0; ks < KS; ks++) {
        uint32_t ah[MT][4], al[MT][4], bh[NT2][4], bl[NT2][4];
#pragma unroll
        for (int mi = 0; mi < MT; mi++) {
            uint32_t off = (uint32_t)(mi * 16 * SAs + ks * 16) * 2;
            ldsm_x4(ah[mi], aH + off);
            ldsm_x4(al[mi], aL + off);
        }
#pragma unroll
        for (int nb = 0; nb < NT2; nb++) {
            uint32_t off = (uint32_t)(nb * 16 * SBs + ks * 16) * 2;
            ldsm_x4(bh[nb], bH + off);
            ldsm_x4(bl[nb], bL + off);
        }
#pragma unroll
        for (int p = 0; p < 3; p++)
#pragma unroll
            for (int mi = 0; mi < MT; mi++)
#pragma unroll
                for (int nb = 0; nb < NT2; nb++)
#pragma unroll
                    for (int half = 0; half < 2; half++) {
                        float* d = acc + (mi * (NT2 * 2) + nb * 2 + half) * 4;
                        const uint32_t* ap = (p == 1) ? al[mi] : ah[mi];
                        const uint32_t* bp = (p == 2) ? &bl[nb][half * 2] : &bh[nb][half * 2];
                        mma_bf16(d, ap, bp);
                    }
    }
}

// fp32 LayerNorm rows -> fp32 dst
__device__ __forceinline__ void ln_rows(const float* __restrict__ src, float* __restrict__ dst,
                                        const float* __restrict__ g, const float* __restrict__ bta,
                                        int lane, int warp, bool do_gelu) {
    for (int n = warp; n < NCELLS; n += NWARPS) {
        const float* r = src + n * DM;
        float v[4];
#pragma unroll
        for (int i = 0; i < 4; i++) v[i] = r[lane + 32 * i];
        float m = warp_sum(v[0] + v[1] + v[2] + v[3]) * (1.0f / DM);
        float var = 0.0f;
#pragma unroll
        for (int i = 0; i < 4; i++) { v[i] -= m; var += v[i] * v[i]; }
        var = warp_sum(var) * (1.0f / DM);
        float inv = rsqrtf(var + 1e-5f);
        float* o = dst + n * DM;
#pragma unroll
        for (int i = 0; i < 4; i++) {
            int d = lane + 32 * i;
            float y = v[i] * inv * g[d] + bta[d];
            o[d] = do_gelu ? gelu_exact(y) : y;
        }
    }
}

// LN -> bf16 hi/lo split [128][SA]; rows >= NCELLS zeroed
__device__ __forceinline__ void ln_split(const float* __restrict__ src,
                                         __nv_bfloat16* __restrict__ aH,
                                         __nv_bfloat16* __restrict__ aL,
                                         const float* __restrict__ g, const float* __restrict__ bta,
                                         int lane, int warp) {
    for (int n = warp; n < 128; n += NWARPS) {
        float y[4] = {0.f, 0.f, 0.f, 0.f};
        if (n < NCELLS) {
            const float* r = src + n * DM;
            float v[4];
#pragma unroll
            for (int i = 0; i < 4; i++) v[i] = r[lane + 32 * i];
            float m = warp_sum(v[0] + v[1] + v[2] + v[3]) * (1.0f / DM);
            float var = 0.0f;
#pragma unroll
            for (int i = 0; i < 4; i++) { v[i] -= m; var += v[i] * v[i]; }
            var = warp_sum(var) * (1.0f / DM);
            float inv = rsqrtf(var + 1e-5f);
#pragma unroll
            for (int i = 0; i < 4; i++) y[i] = v[i] * inv * g[lane + 32 * i] + bta[lane + 32 * i];
        }
#pragma unroll
        for (int i = 0; i < 4; i++) {
            int d = lane + 32 * i;
            __nv_bfloat16 h = __float2bfloat16(y[i]);
            __nv_bfloat16 l = __float2bfloat16(y[i] - __bfloat162float(h));
            aH[n * SA + d] = h;
            aL[n * SA + d] = l;
        }
    }
}

// ---------------- weight preprocessing ----------------
__global__ void prep_kernel(const float* __restrict__ gat_W,
                            const float* __restrict__ ff_W1,
                            const float* __restrict__ ff_W2) {
    const int PER = 147456;
    int e = blockIdx.x * 256 + threadIdx.x;
    if (e >= NL * PER) return;
    int li = e / PER, r = e % PER;
    float w; size_t dst; __nv_bfloat16 *ph, *pl;
    if (r < 16384) {                       // gat: [n 128][k 128] from W[k][n]
        int n = r >> 7, k = r & 127;
        w = gat_W[(size_t)li * 16384 + k * 128 + n];
        dst = (size_t)li * 16384 + n * 128 + k;
        ph = g_gatWh; pl = g_gatWl;
    } else if (r < 81920) {                // W1: [n 512][k 128] from W1[k][n]
        int e2 = r - 16384; int n = e2 >> 7, k = e2 & 127;
        w = ff_W1[(size_t)li * 65536 + k * 512 + n];
        dst = (size_t)li * 65536 + n * 128 + k;
        ph = g_W1h; pl = g_W1l;
    } else {                               // W2 dense per chunk: [li][c][n][kk] from W2[k][n]
        int e2 = r - 81920; int n = e2 >> 9, k = e2 & 511;
        int c = k >> 6, kk = k & 63;
        w = ff_W2[(size_t)li * 65536 + k * 128 + n];
        dst = ((size_t)li * 8 + c) * 8192 + n * 64 + kk;
        ph = g_W2h; pl = g_W2l;
    }
    __nv_bfloat16 h = __float2bfloat16(w);
    __nv_bfloat16 l = __float2bfloat16(w - __bfloat162float(h));
    ph[dst] = h; pl[dst] = l;
}

// ---------------- main kernel ----------------
__global__ __launch_bounds__(NTHREADS, 1)
void gateau_mma(const float* __restrict__ x,
                const float* __restrict__ enc_W,  const float* __restrict__ enc_b,
                const float* __restrict__ enc_ln_g, const float* __restrict__ enc_ln_b,
                const float* __restrict__ ln1_g,  const float* __restrict__ ln1_b,
                const float* __restrict__ a_src,  const float* __restrict__ a_dst,
                const float* __restrict__ ln2_g,  const float* __restrict__ ln2_b,
                const float* __restrict__ ff_b1,  const float* __restrict__ ff_b2,
                const float* __restrict__ fn_g,   const float* __restrict__ fn_b,
                float* __restrict__ out) {
    extern __shared__ char smem[];
    float* sh   = (float*)(smem + OFF_SH);
    float* ssrc = (float*)(smem + OFF_SSRC);
    float* sdst = (float*)(smem + OFF_SDST);
    __nv_bfloat16* Ah  = (__nv_bfloat16*)(smem + OFF_AH);
    __nv_bfloat16* Al  = (__nv_bfloat16*)(smem + OFF_AL);
    __nv_bfloat16* Wh  = (__nv_bfloat16*)(smem + OFF_WH);   // [64][136] or gatW hi [128][136] or W2 hi [128][72]
    __nv_bfloat16* Wl  = (__nv_bfloat16*)(smem + OFF_WL);
    __nv_bfloat16* A2h = (__nv_bfloat16*)(smem + OFF_A2H);  // hidden hi [128][72] or gatW lo [128][136]
    __nv_bfloat16* A2l = (__nv_bfloat16*)(smem + OFF_A2L);
    float* sbufA = (float*)(smem + OFF_AH);   // GAT output fp32 [128][129] / enc temp

    const int b = blockIdx.x;
    const int tid = threadIdx.x;
    const int lane = tid & 31;
    const int warp = tid >> 5;
    const int mw = warp >> 2;       // 0..7 (one m16 tile)
    const int nw = warp & 3;        // 0..3
    const int lr = lane >> 2;       // 0..7
    const int lc = (lane & 3) * 2;  // 0,2,4,6

    const uint32_t uWh = s2u(Wh), uWl = s2u(Wl);
    const uint32_t uA2h = s2u(A2h), uA2l = s2u(A2l);

    // -------- encoder --------
    {
        const float* xb = x + (size_t)b * NCELLS * 6;
        for (int idx = tid; idx < NCELLS * DM; idx += NTHREADS) {
            int n = idx >> 7, d = idx & 127;
            float acc = enc_b[d];
#pragma unroll
            for (int k = 0; k < 6; k++) acc += xb[n * 6 + k] * enc_W[k * DM + d];
            sbufA[idx] = acc;
        }
    }
    __syncthreads();
    ln_rows(sbufA, sh, enc_ln_g, enc_ln_b, lane, warp, true);
    __syncthreads();

    // -------- layers --------
    for (int li = 0; li < NL; li++) {
        // LN1 -> A splits
        ln_split(sh, Ah, Al, ln1_g + li * DM, ln1_b + li * DM, lane, warp);

        // stage FULL gatW: hi -> W region [128][136], lo -> A2 region [128][136]
        {
            const float4* s0 = (const float4*)(g_gatWh + (size_t)li * 16384);
            const float4* s1 = (const float4*)(g_gatWl + (size_t)li * 16384);
            for (int i = tid; i < 2048; i += NTHREADS) {
                int r = i >> 4, j = i & 15;
                uint32_t d = (uint32_t)(r * 17 + j) * 16;
                cp16(uWh + d, s0 + i);
                cp16(uA2h + d, s1 + i);
            }
        }
        CP_WAIT_ALL();
        __syncthreads();

        // ---- GAT projection: one shot, warp tile 16 x 32 ----
        float accG[16];
#pragma unroll
        for (int i = 0; i < 16; i++) accG[i] = 0.f;
        gemm3<1, 2, 8, SA, SW>(Ah, Al, Wh, A2h, mw * 16, nw * 32, lane, accG);
        __syncthreads();

        // epilogue: GAT out fp32 stride 129 over A region
#pragma unroll
        for (int nb = 0; nb < 2; nb++)
#pragma unroll
            for (int half = 0; half < 2; half++) {
                int col = nw * 32 + nb * 16 + half * 8 + lc;
                const float* d = accG + (nb * 2 + half) * 4;
#pragma unroll
                for (int h = 0; h < 2; h++) {
                    int row = mw * 16 + lr + h * 8;
                    sbufA[row * SBUF_STRIDE + col]     = d[h * 2];
                    sbufA[row * SBUF_STRIDE + col + 1] = d[h * 2 + 1];
                }
            }
        __syncthreads();

        // attention scores
        for (int it = tid; it < NCELLS * NH; it += NTHREADS) {
            int n = it >> 2, hh = it & 3;
            const float* hp = sbufA + n * SBUF_STRIDE + hh * 32;
            const float* as = a_src + ((size_t)li * NH + hh) * 32;
            const float* ad = a_dst + ((size_t)li * NH + hh) * 32;
            float s1 = 0.f, s2 = 0.f;
#pragma unroll
            for (int k = 0; k < 32; k++) { float v = hp[k]; s1 += v * as[k]; s2 += v * ad[k]; }
            ssrc[it] = s1; sdst[it] = s2;
        }
        __syncthreads();

        // softmax aggregation over <=6 hex neighbors; += into residual sh
        for (int n = warp; n < NCELLS; n += NWARPS) {
            int q = n / 11, r = n - 11 * q;
            const int dq[6] = { 1, -1, 0, 0, 1, -1 };
            const int dr[6] = { 0, 0, 1, -1, -1, 1 };
            int js[6]; int cnt = 0;
#pragma unroll
            for (int e = 0; e < 6; e++) {
                int nq = q + dq[e], nr = r + dr[e];
                if (nq >= 0 && nq < 11 && nr >= 0 && nr < 11) js[cnt++] = nq * 11 + nr;
            }
#pragma unroll
            for (int hh = 0; hh < NH; hh++) {
                float sd = sdst[n * NH + hh];
                float ex[6]; float m = -1e30f;
                for (int c = 0; c < cnt; c++) {
                    float e = ssrc[js[c] * NH + hh] + sd;
                    e = (e > 0.f) ? e : 0.2f * e;
                    ex[c] = e; m = fmaxf(m, e);
                }
                float s = 0.f;
                for (int c = 0; c < cnt; c++) { ex[c] = expf(ex[c] - m); s += ex[c]; }
                float inv = 1.0f / (s + 1e-10f);
                float acc = 0.f;
                for (int c = 0; c < cnt; c++)
                    acc += ex[c] * inv * sbufA[js[c] * SBUF_STRIDE + hh * 32 + lane];
                sh[n * DM + hh * 32 + lane] += acc;
            }
        }
        __syncthreads();

        // LN2 -> A splits
        ln_split(sh, Ah, Al, ln2_g + li * DM, ln2_b + li * DM, lane, warp);
        __syncthreads();

        // ---- FFN: 8 hidden chunks of 64; FFN2 accumulates in registers ----
        float accF2[16];
#pragma unroll
        for (int i = 0; i < 16; i++) accF2[i] = 0.f;

        for (int c = 0; c < 8; c++) {
            // stage W1 chunk [64][128] -> [64][136] hi/lo (cp.async)
            {
                const float4* s0 = (const float4*)(g_W1h + ((size_t)li * FF + c * 64) * 128);
                const float4* s1 = (const float4*)(g_W1l + ((size_t)li * FF + c * 64) * 128);
                for (int i = tid; i < 1024; i += NTHREADS) {
                    int r = i >> 4, j = i & 15;
                    uint32_t d = (uint32_t)(r * 17 + j) * 16;
                    cp16(uWh + d, s0 + i);
                    cp16(uWl + d, s1 + i);
                }
            }
            CP_WAIT_ALL();
            __syncthreads();

            // FFN1: hidden[128][64] = A @ W1c^T  (warp tile 16 x 16)
            float accF1[8];
#pragma unroll
            for (int i = 0; i < 8; i++) accF1[i] = 0.f;
            gemm3<1, 1, 8, SA, SW>(Ah, Al, Wh, Wl, mw * 16, nw * 16, lane, accF1);
            __syncthreads();   // all warps done reading W1

            // issue W2 chunk cp.asyncs FIRST (dense [128][64] -> [128][72] hi/lo)
            {
                const float4* s0 = (const float4*)(g_W2h + ((size_t)li * 8 + c) * 8192);
                const float4* s1 = (const float4*)(g_W2l + ((size_t)li * 8 + c) * 8192);
                for (int i = tid; i < 1024; i += NTHREADS) {
                    int n = i >> 3, j = i & 7;
                    uint32_t d = (uint32_t)(n * 9 + j) * 16;
                    cp16(uWh + d, s0 + i);
                    cp16(uWl + d, s1 + i);
                }
            }

            // epilogue overlaps W2 transfer: + b1, gelu, split -> A2 (bf16 [128][72])
            {
                const float* b1p = ff_b1 + (size_t)li * FF + c * 64;
#pragma unroll
                for (int half = 0; half < 2; half++) {
                    int col = nw * 16 + half * 8 + lc;
                    float bb0 = __ldg(b1p + col), bb1 = __ldg(b1p + col + 1);
                    const float* d = accF1 + half * 4;
#pragma unroll
                    for (int h = 0; h < 2; h++) {
                        int row = mw * 16 + lr + h * 8;
                        float v0 = gelu_exact(d[h * 2] + bb0);
                        float v1 = gelu_exact(d[h * 2 + 1] + bb1);
                        __nv_bfloat16 h0 = __float2bfloat16(v0);
                        __nv_bfloat16 h1 = __float2bfloat16(v1);
                        __nv_bfloat16 l0 = __float2bfloat16(v0 - __bfloat162float(h0));
                        __nv_bfloat16 l1 = __float2bfloat16(v1 - __bfloat162float(h1));
                        uint32_t ph = ((uint32_t)__bfloat16_as_ushort(h1) << 16) | __bfloat16_as_ushort(h0);
                        uint32_t pl = ((uint32_t)__bfloat16_as_ushort(l1) << 16) | __bfloat16_as_ushort(l0);
                        *(uint32_t*)((char*)A2h + (row * S2 + col) * 2) = ph;
                        *(uint32_t*)((char*)A2l + (row * S2 + col) * 2) = pl;
                    }
                }
            }
            CP_WAIT_ALL();
            __syncthreads();

            // FFN2: accumulate out[128][128] += hidden_c @ W2c^T (warp tile 16 x 32)
            gemm3<1, 2, 4, S2, S2>(A2h, A2l, Wh, Wl, mw * 16, nw * 32, lane, accF2);
            __syncthreads();
        }

        // FFN2 epilogue: sh += acc + b2
        {
            const float* b2p = ff_b2 + (size_t)li * DM;
#pragma unroll
            for (int nb = 0; nb < 2; nb++)
#pragma unroll
                for (int half = 0; half < 2; half++) {
                    int col = nw * 32 + nb * 16 + half * 8 + lc;
                    float bb0 = __ldg(b2p + col), bb1 = __ldg(b2p + col + 1);
                    const float* d = accF2 + (nb * 2 + half) * 4;
#pragma unroll
                    for (int h = 0; h < 2; h++) {
                        int row = mw * 16 + lr + h * 8;
                        if (row < NCELLS) {
                            sh[row * DM + col]     += d[h * 2] + bb0;
                            sh[row * DM + col + 1] += d[h * 2 + 1] + bb1;
                        }
                    }
                }
        }
        __syncthreads();
    }

    // -------- final LN -> out --------
    ln_rows(sh, out + (size_t)b * NCELLS * DM, fn_g, fn_b, lane, warp, false);
}

extern "C" void kernel_launch(void* const* d_in, const int* in_sizes, int n_in,
                              void* d_out, int out_size) {
    const float* x        = (const float*)d_in[0];
    const float* enc_W    = (const float*)d_in[1];
    const float* enc_b    = (const float*)d_in[2];
    const float* enc_ln_g = (const float*)d_in[3];
    const float* enc_ln_b = (const float*)d_in[4];
    const float* ln1_g    = (const float*)d_in[5];
    const float* ln1_b    = (const float*)d_in[6];
    const float* gat_W    = (const float*)d_in[7];
    const float* a_src    = (const float*)d_in[8];
    const float* a_dst    = (const float*)d_in[9];
    const float* ln2_g    = (const float*)d_in[10];
    const float* ln2_b    = (const float*)d_in[11];
    const float* ff_W1    = (const float*)d_in[12];
    const float* ff_b1    = (const float*)d_in[13];
    const float* ff_W2    = (const float*)d_in[14];
    const float* ff_b2    = (const float*)d_in[15];
    const float* fn_g     = (const float*)d_in[16];
    const float* fn_b     = (const float*)d_in[17];
    // d_in[18] = edge_index — derived arithmetically on-device.

    prep_kernel<<<(NL * 147456 + 255) / 256, 256>>>(gat_W, ff_W1, ff_W2);

    cudaFuncSetAttribute(gateau_mma, cudaFuncAttributeMaxDynamicSharedMemorySize, SMEM_TOTAL);
    gateau_mma<<<BATCH, NTHREADS, SMEM_TOTAL>>>(
        x, enc_W, enc_b, enc_ln_g, enc_ln_b,
        ln1_g, ln1_b, a_src, a_dst,
        ln2_g, ln2_b, ff_b1, ff_b2,
        fn_g, fn_b, (float*)d_out);
}

// round 15
// speedup vs baseline: 5.9301x; 1.0223x over previous
#include <cuda_runtime.h>
#include <cuda_bf16.h>
#include <math.h>
#include <stdint.h>

#define NCELLS 121
#define DM 128
#define NH 4
#define NL 6
#define FF 512
#define BATCH 256
#define NTHREADS 1024
#define NWARPS 32

// ---------------- smem byte offsets ----------------
#define OFF_SH    0          // residual fp32 [121][128] = 61952
#define OFF_SSRC  61952
#define OFF_SDST  63888
#define OFF_AH    66048      // A hi bf16 [128][136]  (also GAT out fp32 [128][129] / enc temp)
#define OFF_AL    100864     // A lo bf16 [128][136]
#define OFF_S0    135680     // W slot 0 (18432)  | S0+S1 contiguous = gatW-hi [128][136]
#define OFF_S1    154112     // W slot 1 (18432)
#define OFF_A2H   172544     // hidden hi [128][72] | gatW-lo half1
#define OFF_A2L   190976     // hidden lo [128][72] | gatW-lo half2
#define OFF_F     209408     // W2-hi slot (18432)
#define SMEM_TOTAL 227840

#define SA 136   // A row stride (bf16 elems)
#define SW 136   // W1/GAT row stride
#define S2 72    // A2 / W2 row stride
#define SBUF_STRIDE 129

// ---------------- preprocessed weights ----------------
__device__ __align__(16) __nv_bfloat16 g_gatWh[NL*128*128];
__device__ __align__(16) __nv_bfloat16 g_gatWl[NL*128*128];
__device__ __align__(16) __nv_bfloat16 g_W1h[NL*FF*128];
__device__ __align__(16) __nv_bfloat16 g_W1l[NL*FF*128];
__device__ __align__(16) __nv_bfloat16 g_W2h[NL*8*128*64];   // dense per chunk [li][c][n 128][kk 64]
__device__ __align__(16) __nv_bfloat16 g_W2l[NL*8*128*64];

// ---------------- helpers ----------------
__device__ __forceinline__ float warp_sum(float v) {
#pragma unroll
    for (int o = 16; o; o >>= 1) v += __shfl_xor_sync(0xffffffffu, v, o);
    return v;
}
__device__ __forceinline__ float gelu_exact(float x) {
    return 0.5f * x * (1.0f + erff(x * 0.70710678118654752440f));
}
__device__ __forceinline__ void mma_bf16(float* d, const uint32_t* a, const uint32_t* b) {
    asm volatile("mma.sync.aligned.m16n8k16.row.col.f32.bf16.bf16.f32 "
                 "{%0,%1,%2,%3}, {%4,%5,%6,%7}, {%8,%9}, {%0,%1,%2,%3};"
                 : "+f"(d[0]), "+f"(d[1]), "+f"(d[2]), "+f"(d[3])
                 : "r"(a[0]), "r"(a[1]), "r"(a[2]), "r"(a[3]), "r"(b[0]), "r"(b[1]));
}
__device__ __forceinline__ void ldsm_x4(uint32_t* r, uint32_t addr) {
    asm volatile("ldmatrix.sync.aligned.m8n8.x4.shared.b16 {%0,%1,%2,%3}, [%4];"
                 : "=r"(r[0]), "=r"(r[1]), "=r"(r[2]), "=r"(r[3]) : "r"(addr));
}
__device__ __forceinline__ void cp16(uint32_t dst, const void* src) {
    asm volatile("cp.async.cg.shared.global [%0], [%1], 16;" :: "r"(dst), "l"(src));
}
#define CP_WAIT_ALL() asm volatile("cp.async.wait_all;" ::: "memory")
__device__ __forceinline__ uint32_t s2u(const void* p) {
    return (uint32_t)__cvta_generic_to_shared(p);
}

// 3-pass split GEMM warp tile, ldmatrix loads, pass-outer MMA order for ILP.
// MT m16-tiles x NT2 n16-blocks, KS k16 steps. acc[(mi*NT2*2 + nb*2 + half)*4 +{0..3}]
// B hi/lo may live in different buffers (bH base vs bL base passed separately).
template<int MT, int NT2, int KS, int SAs, int SBs>
__device__ __forceinline__ void gemm3(uint32_t uAh, uint32_t uAl,
                                      uint32_t uBh, uint32_t uBl,
                                      int m0, int n0, int lane, float* acc) {
    const int blk = lane >> 3, rib = lane & 7;
    const int a_elem = (m0 + (blk & 1) * 8 + rib) * SAs + (blk >> 1) * 8;
    const int b_elem = (n0 + (blk >> 1) * 8 + rib) * SBs + (blk & 1) * 8;
    const uint32_t aH = uAh + a_elem * 2;
    const uint32_t aL = uAl + a_elem * 2;
    const uint32_t bH = uBh + b_elem * 2;
    const uint32_t bL = uBl + b_elem * 2;

#pragma unroll
    for (int ks = 0; ks < KS; ks++) {
        uint32_t ah[MT][4], al[MT][4], bh[NT2][4], bl[NT2][4];
#pragma unroll
        for (int mi = 0; mi < MT; mi++) {
            uint32_t off = (uint32_t)(mi * 16 * SAs + ks * 16) * 2;
            ldsm_x4(ah[mi], aH + off);
            ldsm_x4(al[mi], aL + off);
        }
#pragma unroll
        for (int nb = 0; nb < NT2; nb++) {
            uint32_t off = (uint32_t)(nb * 16 * SBs + ks * 16) * 2;
            ldsm_x4(bh[nb], bH + off);
            ldsm_x4(bl[nb], bL + off);
        }
#pragma unroll
        for (int p = 0; p < 3; p++)
#pragma unroll
            for (int mi = 0; mi < MT; mi++)
#pragma unroll
                for (int nb = 0; nb < NT2; nb++)
#pragma unroll
                    for (int half = 0; half < 2; half++) {
                        float* d = acc + (mi * (NT2 * 2) + nb * 2 + half) * 4;
                        const uint32_t* ap = (p == 1) ? al[mi] : ah[mi];
                        const uint32_t* bp = (p == 2) ? &bl[nb][half * 2] : &bh[nb][half * 2];
                        mma_bf16(d, ap, bp);
                    }
    }
}

// fp32 LayerNorm rows -> fp32 dst
__device__ __forceinline__ void ln_rows(const float* __restrict__ src, float* __restrict__ dst,
                                        const float* __restrict__ g, const float* __restrict__ bta,
                                        int lane, int warp, bool do_gelu) {
    for (int n = warp; n < NCELLS; n += NWARPS) {
        const float* r = src + n * DM;
        float v[4];
#pragma unroll
        for (int i = 0; i < 4; i++) v[i] = r[lane + 32 * i];
        float m = warp_sum(v[0] + v[1] + v[2] + v[3]) * (1.0f / DM);
        float var = 0.0f;
#pragma unroll
        for (int i = 0; i < 4; i++) { v[i] -= m; var += v[i] * v[i]; }
        var = warp_sum(var) * (1.0f / DM);
        float inv = rsqrtf(var + 1e-5f);
        float* o = dst + n * DM;
#pragma unroll
        for (int i = 0; i < 4; i++) {
            int d = lane + 32 * i;
            float y = v[i] * inv * g[d] + bta[d];
            o[d] = do_gelu ? gelu_exact(y) : y;
        }
    }
}

// LN -> bf16 hi/lo split [128][SA]; rows >= NCELLS zeroed
__device__ __forceinline__ void ln_split(const float* __restrict__ src,
                                         __nv_bfloat16* __restrict__ aH,
                                         __nv_bfloat16* __restrict__ aL,
                                         const float* __restrict__ g, const float* __restrict__ bta,
                                         int lane, int warp) {
    for (int n = warp; n < 128; n += NWARPS) {
        float y[4] = {0.f, 0.f, 0.f, 0.f};
        if (n < NCELLS) {
            const float* r = src + n * DM;
            float v[4];
#pragma unroll
            for (int i = 0; i < 4; i++) v[i] = r[lane + 32 * i];
            float m = warp_sum(v[0] + v[1] + v[2] + v[3]) * (1.0f / DM);
            float var = 0.0f;
#pragma unroll
            for (int i = 0; i < 4; i++) { v[i] -= m; var += v[i] * v[i]; }
            var = warp_sum(var) * (1.0f / DM);
            float inv = rsqrtf(var + 1e-5f);
#pragma unroll
            for (int i = 0; i < 4; i++) y[i] = v[i] * inv * g[lane + 32 * i] + bta[lane + 32 * i];
        }
#pragma unroll
        for (int i = 0; i < 4; i++) {
            int d = lane + 32 * i;
            __nv_bfloat16 h = __float2bfloat16(y[i]);
            __nv_bfloat16 l = __float2bfloat16(y[i] - __bfloat162float(h));
            aH[n * SA + d] = h;
            aL[n * SA + d] = l;
        }
    }
}

// stage W1 chunk part ([64][128] -> [64][136]) via cp.async
__device__ __forceinline__ void stage_w1(uint32_t dst, const __nv_bfloat16* src, int tid) {
    const float4* s = (const float4*)src;
    for (int i = tid; i < 1024; i += NTHREADS) {
        int r = i >> 4, j = i & 15;
        cp16(dst + (uint32_t)(r * 17 + j) * 16, s + i);
    }
}
// stage W2 chunk part (dense [128][64] -> [128][72])
__device__ __forceinline__ void stage_w2(uint32_t dst, const __nv_bfloat16* src, int tid) {
    const float4* s = (const float4*)src;
    for (int i = tid; i < 1024; i += NTHREADS) {
        int n = i >> 3, j = i & 7;
        cp16(dst + (uint32_t)(n * 9 + j) * 16, s + i);
    }
}

// ---------------- weight preprocessing ----------------
__global__ void prep_kernel(const float* __restrict__ gat_W,
                            const float* __restrict__ ff_W1,
                            const float* __restrict__ ff_W2) {
    const int PER = 147456;
    int e = blockIdx.x * 256 + threadIdx.x;
    if (e >= NL * PER) return;
    int li = e / PER, r = e % PER;
    float w; size_t dst; __nv_bfloat16 *ph, *pl;
    if (r < 16384) {                       // gat: [n 128][k 128] from W[k][n]
        int n = r >> 7, k = r & 127;
        w = gat_W[(size_t)li * 16384 + k * 128 + n];
        dst = (size_t)li * 16384 + n * 128 + k;
        ph = g_gatWh; pl = g_gatWl;
    } else if (r < 81920) {                // W1: [n 512][k 128] from W1[k][n]
        int e2 = r - 16384; int n = e2 >> 7, k = e2 & 127;
        w = ff_W1[(size_t)li * 65536 + k * 512 + n];
        dst = (size_t)li * 65536 + n * 128 + k;
        ph = g_W1h; pl = g_W1l;
    } else {                               // W2 dense per chunk: [li][c][n][kk] from W2[k][n]
        int e2 = r - 81920; int n = e2 >> 9, k = e2 & 511;
        int c = k >> 6, kk = k & 63;
        w = ff_W2[(size_t)li * 65536 + k * 128 + n];
        dst = ((size_t)li * 8 + c) * 8192 + n * 64 + kk;
        ph = g_W2h; pl = g_W2l;
    }
    __nv_bfloat16 h = __float2bfloat16(w);
    __nv_bfloat16 l = __float2bfloat16(w - __bfloat162float(h));
    ph[dst] = h; pl[dst] = l;
}

// ---------------- main kernel ----------------
__global__ __launch_bounds__(NTHREADS, 1)
void gateau_mma(const float* __restrict__ x,
                const float* __restrict__ enc_W,  const float* __restrict__ enc_b,
                const float* __restrict__ enc_ln_g, const float* __restrict__ enc_ln_b,
                const float* __restrict__ ln1_g,  const float* __restrict__ ln1_b,
                const float* __restrict__ a_src,  const float* __restrict__ a_dst,
                const float* __restrict__ ln2_g,  const float* __restrict__ ln2_b,
                const float* __restrict__ ff_b1,  const float* __restrict__ ff_b2,
                const float* __restrict__ fn_g,   const float* __restrict__ fn_b,
                float* __restrict__ out) {
    extern __shared__ char smem[];
    float* sh   = (float*)(smem + OFF_SH);
    float* ssrc = (float*)(smem + OFF_SSRC);
    float* sdst = (float*)(smem + OFF_SDST);
    __nv_bfloat16* Ah  = (__nv_bfloat16*)(smem + OFF_AH);
    __nv_bfloat16* Al  = (__nv_bfloat16*)(smem + OFF_AL);
    __nv_bfloat16* A2h = (__nv_bfloat16*)(smem + OFF_A2H);
    __nv_bfloat16* A2l = (__nv_bfloat16*)(smem + OFF_A2L);
    float* sbufA = (float*)(smem + OFF_AH);   // GAT output fp32 [128][129] / enc temp

    const int b = blockIdx.x;
    const int tid = threadIdx.x;
    const int lane = tid & 31;
    const int warp = tid >> 5;
    const int mw = warp >> 2;       // 0..7
    const int nw = warp & 3;        // 0..3
    const int lr = lane >> 2;       // 0..7
    const int lc = (lane & 3) * 2;  // 0,2,4,6

    const uint32_t uAh = s2u(Ah), uAl = s2u(Al);
    const uint32_t uS0 = s2u(smem + OFF_S0), uS1 = s2u(smem + OFF_S1);
    const uint32_t uA2h = s2u(A2h), uA2l = s2u(A2l);
    const uint32_t uF = s2u(smem + OFF_F);

    // -------- encoder --------
    {
        const float* xb = x + (size_t)b * NCELLS * 6;
        for (int idx = tid; idx < NCELLS * DM; idx += NTHREADS) {
            int n = idx >> 7, d = idx & 127;
            float acc = enc_b[d];
#pragma unroll
            for (int k = 0; k < 6; k++) acc += xb[n * 6 + k] * enc_W[k * DM + d];
            sbufA[idx] = acc;
        }
    }
    __syncthreads();
    ln_rows(sbufA, sh, enc_ln_g, enc_ln_b, lane, warp, true);
    __syncthreads();

    // -------- layers --------
    for (int li = 0; li < NL; li++) {
        // issue GAT W staging FIRST (hi -> S0+S1 contiguous [128][136], lo -> A2 region)
        {
            const float4* s0 = (const float4*)(g_gatWh + (size_t)li * 16384);
            const float4* s1 = (const float4*)(g_gatWl + (size_t)li * 16384);
            for (int i = tid; i < 2048; i += NTHREADS) {
                int r = i >> 4, j = i & 15;
                uint32_t d = (uint32_t)(r * 17 + j) * 16;
                cp16(uS0 + d, s0 + i);
                cp16(uA2h + d, s1 + i);
            }
        }
        // LN1 -> A splits (overlaps the weight fetch)
        ln_split(sh, Ah, Al, ln1_g + li * DM, ln1_b + li * DM, lane, warp);
        CP_WAIT_ALL();
        __syncthreads();

        // ---- GAT projection: warp tile 16 x 32 ----
        float accG[16];
#pragma unroll
        for (int i = 0; i < 16; i++) accG[i] = 0.f;
        gemm3<1, 2, 8, SA, SW>(uAh, uAl, uS0, uA2h, mw * 16, nw * 32, lane, accG);
        __syncthreads();

        // issue W1(0) staging now (S0/S1 free) — overlaps epilogue+attention+LN2
        stage_w1(uS0, g_W1h + (size_t)li * FF * 128, tid);
        stage_w1(uS1, g_W1l + (size_t)li * FF * 128, tid);

        // epilogue: GAT out fp32 stride 129 over A region
#pragma unroll
        for (int nb = 0; nb < 2; nb++)
#pragma unroll
            for (int half = 0; half < 2; half++) {
                int col = nw * 32 + nb * 16 + half * 8 + lc;
                const float* d = accG + (nb * 2 + half) * 4;
#pragma unroll
                for (int h = 0; h < 2; h++) {
                    int row = mw * 16 + lr + h * 8;
                    sbufA[row * SBUF_STRIDE + col]     = d[h * 2];
                    sbufA[row * SBUF_STRIDE + col + 1] = d[h * 2 + 1];
                }
            }
        __syncthreads();

        // attention scores
        for (int it = tid; it < NCELLS * NH; it += NTHREADS) {
            int n = it >> 2, hh = it & 3;
            const float* hp = sbufA + n * SBUF_STRIDE + hh * 32;
            const float* as = a_src + ((size_t)li * NH + hh) * 32;
            const float* ad = a_dst + ((size_t)li * NH + hh) * 32;
            float s1 = 0.f, s2 = 0.f;
#pragma unroll
            for (int k = 0; k < 32; k++) { float v = hp[k]; s1 += v * as[k]; s2 += v * ad[k]; }
            ssrc[it] = s1; sdst[it] = s2;
        }
        __syncthreads();

        // softmax aggregation over <=6 hex neighbors; += into residual sh
        for (int n = warp; n < NCELLS; n += NWARPS) {
            int q = n / 11, r = n - 11 * q;
            const int dq[6] = { 1, -1, 0, 0, 1, -1 };
            const int dr[6] = { 0, 0, 1, -1, -1, 1 };
            int js[6]; int cnt = 0;
#pragma unroll
            for (int e = 0; e < 6; e++) {
                int nq = q + dq[e], nr = r + dr[e];
                if (nq >= 0 && nq < 11 && nr >= 0 && nr < 11) js[cnt++] = nq * 11 + nr;
            }
#pragma unroll
            for (int hh = 0; hh < NH; hh++) {
                float sd = sdst[n * NH + hh];
                float ex[6]; float m = -1e30f;
                for (int c = 0; c < cnt; c++) {
                    float e = ssrc[js[c] * NH + hh] + sd;
                    e = (e > 0.f) ? e : 0.2f * e;
                    ex[c] = e; m = fmaxf(m, e);
                }
                float s = 0.f;
                for (int c = 0; c < cnt; c++) { ex[c] = expf(ex[c] - m); s += ex[c]; }
                float inv = 1.0f / (s + 1e-10f);
                float acc = 0.f;
                for (int c = 0; c < cnt; c++)
                    acc += ex[c] * inv * sbufA[js[c] * SBUF_STRIDE + hh * 32 + lane];
                sh[n * DM + hh * 32 + lane] += acc;
            }
        }
        __syncthreads();

        // LN2 -> A splits
        ln_split(sh, Ah, Al, ln2_g + li * DM, ln2_b + li * DM, lane, warp);

        // ---- FFN: 8 chunks; 3-slot pipelined weight staging ----
        float accF2[16];
#pragma unroll
        for (int i = 0; i < 16; i++) accF2[i] = 0.f;

        for (int c = 0; c < 8; c++) {
            const uint32_t hiB = (c & 1) ? uS1 : uS0;   // holds W1hi(c)
            const uint32_t loB = (c & 1) ? uS0 : uS1;   // holds W1lo(c)
            CP_WAIT_ALL();      // W1(c) (and, for c=0, also LN overlap) ready
            __syncthreads();

            // FFN1: hidden[128][64] = A @ W1c^T  (warp tile 16 x 16)
            float accF1[8];
#pragma unroll
            for (int i = 0; i < 8; i++) accF1[i] = 0.f;
            gemm3<1, 1, 8, SA, SW>(uAh, uAl, hiB, loB, mw * 16, nw * 16, lane, accF1);
            __syncthreads();   // all warps done reading W1(c); hiB free

            // issue W2(c): hi -> F, lo -> hiB (async under epilogue)
            stage_w2(uF,  g_W2h + ((size_t)li * 8 + c) * 8192, tid);
            stage_w2(hiB, g_W2l + ((size_t)li * 8 + c) * 8192, tid);

            // epilogue: + b1, gelu, split -> A2 (bf16 [128][72])
            {
                const float* b1p = ff_b1 + (size_t)li * FF + c * 64;
#pragma unroll
                for (int half = 0; half < 2; half++) {
                    int col = nw * 16 + half * 8 + lc;
                    float bb0 = __ldg(b1p + col), bb1 = __ldg(b1p + col + 1);
                    const float* d = accF1 + half * 4;
#pragma unroll
                    for (int h = 0; h < 2; h++) {
                        int row = mw * 16 + lr + h * 8;
                        float v0 = gelu_exact(d[h * 2] + bb0);
                        float v1 = gelu_exact(d[h * 2 + 1] + bb1);
                        __nv_bfloat16 h0 = __float2bfloat16(v0);
                        __nv_bfloat16 h1 = __float2bfloat16(v1);
                        __nv_bfloat16 l0 = __float2bfloat16(v0 - __bfloat162float(h0));
                        __nv_bfloat16 l1 = __float2bfloat16(v1 - __bfloat162float(h1));
                        uint32_t ph = ((uint32_t)__bfloat16_as_ushort(h1) << 16) | __bfloat16_as_ushort(h0);
                        uint32_t pl = ((uint32_t)__bfloat16_as_ushort(l1) << 16) | __bfloat16_as_ushort(l0);
                        *(uint32_t*)((char*)A2h + (row * S2 + col) * 2) = ph;
                        *(uint32_t*)((char*)A2l + (row * S2 + col) * 2) = pl;
                    }
                }
            }
            CP_WAIT_ALL();
            __syncthreads();

            // prefetch W1(c+1)-hi into loB (free during MMA2)
            if (c < 7)
                stage_w1(loB, g_W1h + ((size_t)li * FF + (c + 1) * 64) * 128, tid);

            // FFN2: accumulate out[128][128] += hidden_c @ W2c^T (warp tile 16 x 32)
            gemm3<1, 2, 4, S2, S2>(uA2h, uA2l, uF, hiB, mw * 16, nw * 32, lane, accF2);
            __syncthreads();   // MMA2 done; hiB free

            // prefetch W1(c+1)-lo into hiB (= next chunk's loB)
            if (c < 7)
                stage_w1(hiB, g_W1l + ((size_t)li * FF + (c + 1) * 64) * 128, tid);
        }

        // FFN2 epilogue: sh += acc + b2
        {
            const float* b2p = ff_b2 + (size_t)li * DM;
#pragma unroll
            for (int nb = 0; nb < 2; nb++)
#pragma unroll
                for (int half = 0; half < 2; half++) {
                    int col = nw * 32 + nb * 16 + half * 8 + lc;
                    float bb0 = __ldg(b2p + col), bb1 = __ldg(b2p + col + 1);
                    const float* d = accF2 + (nb * 2 + half) * 4;
#pragma unroll
                    for (int h = 0; h < 2; h++) {
                        int row = mw * 16 + lr + h * 8;
                        if (row < NCELLS) {
                            sh[row * DM + col]     += d[h * 2] + bb0;
                            sh[row * DM + col + 1] += d[h * 2 + 1] + bb1;
                        }
                    }
                }
        }
        __syncthreads();
    }

    // -------- final LN -> out --------
    ln_rows(sh, out + (size_t)b * NCELLS * DM, fn_g, fn_b, lane, warp, false);
}

extern "C" void kernel_launch(void* const* d_in, const int* in_sizes, int n_in,
                              void* d_out, int out_size) {
    const float* x        = (const float*)d_in[0];
    const float* enc_W    = (const float*)d_in[1];
    const float* enc_b    = (const float*)d_in[2];
    const float* enc_ln_g = (const float*)d_in[3];
    const float* enc_ln_b = (const float*)d_in[4];
    const float* ln1_g    = (const float*)d_in[5];
    const float* ln1_b    = (const float*)d_in[6];
    const float* gat_W    = (const float*)d_in[7];
    const float* a_src    = (const float*)d_in[8];
    const float* a_dst    = (const float*)d_in[9];
    const float* ln2_g    = (const float*)d_in[10];
    const float* ln2_b    = (const float*)d_in[11];
    const float* ff_W1    = (const float*)d_in[12];
    const float* ff_b1    = (const float*)d_in[13];
    const float* ff_W2    = (const float*)d_in[14];
    const float* ff_b2    = (const float*)d_in[15];
    const float* fn_g     = (const float*)d_in[16];
    const float* fn_b     = (const float*)d_in[17];
    // d_in[18] = edge_index — derived arithmetically on-device.

    prep_kernel<<<(NL * 147456 + 255) / 256, 256>>>(gat_W, ff_W1, ff_W2);

    cudaFuncSetAttribute(gateau_mma, cudaFuncAttributeMaxDynamicSharedMemorySize, SMEM_TOTAL);
    gateau_mma<<<BATCH, NTHREADS, SMEM_TOTAL>>>(
        x, enc_W, enc_b, enc_ln_g, enc_ln_b,
        ln1_g, ln1_b, a_src, a_dst,
        ln2_g, ln2_b, ff_b1, ff_b2,
        fn_g, fn_b, (float*)d_out);
}